// round 2
// baseline (speedup 1.0000x reference)
#include <cuda_runtime.h>
#include <math.h>

#define BATCH 2
#define SEQ   2048
#define DM    1024
#define NH    16
#define HD    64
#define MTOT  (BATCH*SEQ)   // 4096

// Padded row stride for transposed smem tiles: must be multiple of 4 floats
// (16B) so float4 LDS stays aligned. 68 = 64 + 4.
#define PAD 68

// Scratch (allocation-free): intermediates for projected Q/K/V and attention out.
__device__ float g_qh[MTOT * DM];
__device__ float g_kh[MTOT * DM];
__device__ float g_vh[MTOT * DM];
__device__ float g_ao[MTOT * DM];

// ----------------------------------------------------------------------------
// C[M,N] = A[M,K] @ W[K,N] + bias[N];  M=4096, N=K=1024 (all multiples of tile)
// 64x64 tile, BK=16, 256 threads, 4x4 per-thread microtile.
// ----------------------------------------------------------------------------
__global__ __launch_bounds__(256)
void gemm_bias(const float* __restrict__ A, const float* __restrict__ W,
               const float* __restrict__ bias, float* __restrict__ C) {
    const int N = DM, K = DM;
    __shared__ float As[16][PAD];  // k-major transposed A tile (aligned stride)
    __shared__ float Ws[16][64];   // W tile
    const int tid = threadIdx.x;
    const int tx = tid & 15, ty = tid >> 4;
    const int bm = blockIdx.y * 64, bn = blockIdx.x * 64;

    float acc[4][4] = {};

    for (int k0 = 0; k0 < K; k0 += 16) {
        // Load A tile (64x16) transposed into As[k][m]
        #pragma unroll
        for (int r = 0; r < 4; r++) {
            int i  = tid + r * 256;
            int mm = i >> 4, kk = i & 15;
            As[kk][mm] = A[(size_t)(bm + mm) * K + k0 + kk];
        }
        // Load W tile (16x64), one float4 per thread
        {
            int kk = tid >> 4;
            int nn = (tid & 15) * 4;
            *(float4*)&Ws[kk][nn] = *(const float4*)&W[(size_t)(k0 + kk) * N + bn + nn];
        }
        __syncthreads();

        #pragma unroll
        for (int kk = 0; kk < 16; kk++) {
            float4 a4 = *(float4*)&As[kk][ty * 4];
            float4 w4 = *(float4*)&Ws[kk][tx * 4];
            float a[4] = {a4.x, a4.y, a4.z, a4.w};
            float w[4] = {w4.x, w4.y, w4.z, w4.w};
            #pragma unroll
            for (int i = 0; i < 4; i++)
                #pragma unroll
                for (int j = 0; j < 4; j++)
                    acc[i][j] += a[i] * w[j];
        }
        __syncthreads();
    }

    float4 b4 = *(const float4*)&bias[bn + tx * 4];
    float bb[4] = {b4.x, b4.y, b4.z, b4.w};
    #pragma unroll
    for (int i = 0; i < 4; i++) {
        float4 o4;
        o4.x = acc[i][0] + bb[0];
        o4.y = acc[i][1] + bb[1];
        o4.z = acc[i][2] + bb[2];
        o4.w = acc[i][3] + bb[3];
        *(float4*)&C[(size_t)(bm + ty * 4 + i) * N + bn + tx * 4] = o4;
    }
}

// ----------------------------------------------------------------------------
// Causal flash attention, fp32. One CTA = 64 queries of one (batch, head).
// BQ=BK=64, D=64. Online softmax. 256 threads, 4x4 per-thread microtiles.
// Smem: Qt[64][PAD] d-major, KPt[64][PAD] (K d-major, then reused for P k-major),
//       Vs[64][64] k-major.
// ----------------------------------------------------------------------------
#define ATTN_SMEM_FLOATS (2 * 64 * PAD + 64 * 64)

__global__ __launch_bounds__(256)
void attn_kernel(const float* __restrict__ qh, const float* __restrict__ kh,
                 const float* __restrict__ vh, float* __restrict__ out) {
    extern __shared__ float sm[];
    float* Qt  = sm;                // [64][PAD]  Qt[d][q]
    float* KPt = sm + 64 * PAD;     // [64][PAD]  Kt[d][k], later Pt[k][q]
    float* Vs  = sm + 2 * 64 * PAD; // [64][64]   Vs[k][d]

    const int tid = threadIdx.x;
    const int tx = tid & 15, ty = tid >> 4;
    const int q0 = blockIdx.x * 64;
    const int h  = blockIdx.y;
    const int bb = blockIdx.z;

    const float* Qb = qh + (size_t)bb * SEQ * DM + h * HD;
    const float* Kb = kh + (size_t)bb * SEQ * DM + h * HD;
    const float* Vb = vh + (size_t)bb * SEQ * DM + h * HD;

    // Load Q tile transposed (d-major)
    for (int i = tid; i < 64 * 64; i += 256) {
        int q = i >> 6, d = i & 63;
        Qt[d * PAD + q] = Qb[(size_t)(q0 + q) * DM + d];
    }

    float o[4][4] = {};
    float mrow[4], lrow[4];
    #pragma unroll
    for (int i = 0; i < 4; i++) { mrow[i] = -INFINITY; lrow[i] = 0.f; }

    for (int j0 = 0; j0 <= q0; j0 += 64) {
        __syncthreads();  // previous PV reads done; Q load done on first iter
        for (int i = tid; i < 64 * 64; i += 256) {
            int kk = i >> 6, d = i & 63;
            KPt[d * PAD + kk] = Kb[(size_t)(j0 + kk) * DM + d];
            Vs[kk * 64 + d]   = Vb[(size_t)(j0 + kk) * DM + d];
        }
        __syncthreads();

        // S = Q K^T  (4x4 per thread)
        float s[4][4] = {};
        #pragma unroll 8
        for (int d = 0; d < 64; d++) {
            float4 q4 = *(float4*)&Qt[d * PAD + ty * 4];
            float4 k4 = *(float4*)&KPt[d * PAD + tx * 4];
            float a[4] = {q4.x, q4.y, q4.z, q4.w};
            float b[4] = {k4.x, k4.y, k4.z, k4.w};
            #pragma unroll
            for (int i = 0; i < 4; i++)
                #pragma unroll
                for (int j = 0; j < 4; j++)
                    s[i][j] += a[i] * b[j];
        }

        // scale + causal mask (only the diagonal block can mask)
        const bool diag = (j0 == q0);
        #pragma unroll
        for (int i = 0; i < 4; i++)
            #pragma unroll
            for (int j = 0; j < 4; j++) {
                s[i][j] *= 0.125f;  // 1/sqrt(64)
                if (diag && (tx * 4 + j > ty * 4 + i)) s[i][j] = -INFINITY;
            }

        // online softmax (row = 16 tx lanes; xor-shuffles stay in 16-lane groups)
        #pragma unroll
        for (int i = 0; i < 4; i++) {
            float rm = fmaxf(fmaxf(s[i][0], s[i][1]), fmaxf(s[i][2], s[i][3]));
            #pragma unroll
            for (int w = 1; w < 16; w <<= 1)
                rm = fmaxf(rm, __shfl_xor_sync(0xffffffffu, rm, w));
            float mn = fmaxf(mrow[i], rm);
            float alpha = __expf(mrow[i] - mn);
            mrow[i] = mn;
            float rs = 0.f;
            #pragma unroll
            for (int j = 0; j < 4; j++) {
                s[i][j] = __expf(s[i][j] - mn);  // reuse s as P
                rs += s[i][j];
            }
            #pragma unroll
            for (int w = 1; w < 16; w <<= 1)
                rs += __shfl_xor_sync(0xffffffffu, rs, w);
            lrow[i] = lrow[i] * alpha + rs;
            #pragma unroll
            for (int j = 0; j < 4; j++) o[i][j] *= alpha;
        }

        __syncthreads();  // all reads of K tile finished
        // write P into KPt, k-major: Pt[k][q]
        #pragma unroll
        for (int i = 0; i < 4; i++)
            #pragma unroll
            for (int j = 0; j < 4; j++)
                KPt[(tx * 4 + j) * PAD + ty * 4 + i] = s[i][j];
        __syncthreads();

        // O += P @ V
        #pragma unroll 8
        for (int kk = 0; kk < 64; kk++) {
            float4 p4 = *(float4*)&KPt[kk * PAD + ty * 4];
            float4 v4 = *(float4*)&Vs[kk * 64 + tx * 4];
            float p[4] = {p4.x, p4.y, p4.z, p4.w};
            float v[4] = {v4.x, v4.y, v4.z, v4.w};
            #pragma unroll
            for (int i = 0; i < 4; i++)
                #pragma unroll
                for (int j = 0; j < 4; j++)
                    o[i][j] += p[i] * v[j];
        }
    }

    #pragma unroll
    for (int i = 0; i < 4; i++) {
        float inv = 1.f / lrow[i];
        float4 o4 = { o[i][0] * inv, o[i][1] * inv, o[i][2] * inv, o[i][3] * inv };
        *(float4*)&out[((size_t)bb * SEQ + q0 + ty * 4 + i) * DM + h * HD + tx * 4] = o4;
    }
}

// ----------------------------------------------------------------------------
extern "C" void kernel_launch(void* const* d_in, const int* in_sizes, int n_in,
                              void* d_out, int out_size) {
    const float* q  = (const float*)d_in[0];
    const float* k  = (const float*)d_in[1];
    const float* v  = (const float*)d_in[2];
    const float* Wq = (const float*)d_in[3];
    const float* bq = (const float*)d_in[4];
    const float* Wk = (const float*)d_in[5];
    const float* bk = (const float*)d_in[6];
    const float* Wv = (const float*)d_in[7];
    const float* bv = (const float*)d_in[8];
    const float* Wo = (const float*)d_in[9];
    const float* bo = (const float*)d_in[10];
    float* out = (float*)d_out;

    float *qh, *khp, *vhp, *ao;
    cudaGetSymbolAddress((void**)&qh,  g_qh);
    cudaGetSymbolAddress((void**)&khp, g_kh);
    cudaGetSymbolAddress((void**)&vhp, g_vh);
    cudaGetSymbolAddress((void**)&ao,  g_ao);

    dim3 ggrid(DM / 64, MTOT / 64);
    gemm_bias<<<ggrid, 256>>>(q, Wq, bq, qh);
    gemm_bias<<<ggrid, 256>>>(k, Wk, bk, khp);
    gemm_bias<<<ggrid, 256>>>(v, Wv, bv, vhp);

    size_t smem = ATTN_SMEM_FLOATS * sizeof(float);  // 50,944 B > 48K default
    cudaFuncSetAttribute(attn_kernel, cudaFuncAttributeMaxDynamicSharedMemorySize,
                         (int)smem);
    attn_kernel<<<dim3(SEQ / 64, NH, BATCH), 256, smem>>>(qh, khp, vhp, ao);

    gemm_bias<<<ggrid, 256>>>(ao, Wo, bo, out);
}

// round 4
// speedup vs baseline: 2.9853x; 2.9853x over previous
#include <cuda_runtime.h>
#include <math.h>
#include <stdint.h>

#define BATCH 2
#define SEQ   2048
#define DM    1024
#define NH    16
#define HD    64
#define MTOT  (BATCH*SEQ)   // 4096

// Scratch (allocation-free)
__device__ float g_qh[MTOT * DM];
__device__ float g_kh[MTOT * DM];
__device__ float g_vh[MTOT * DM];
__device__ float g_ao[MTOT * DM];

__device__ __forceinline__ uint32_t f2tf(float x) {
    uint32_t r;
    asm("cvt.rna.tf32.f32 %0, %1;" : "=r"(r) : "f"(x));
    return r;
}

__device__ __forceinline__ void mma_tf32(float d[4],
    uint32_t a0, uint32_t a1, uint32_t a2, uint32_t a3,
    uint32_t b0, uint32_t b1) {
    asm volatile(
        "mma.sync.aligned.m16n8k8.row.col.f32.tf32.tf32.f32 "
        "{%0,%1,%2,%3}, {%4,%5,%6,%7}, {%8,%9}, {%0,%1,%2,%3};\n"
        : "+f"(d[0]), "+f"(d[1]), "+f"(d[2]), "+f"(d[3])
        : "r"(a0), "r"(a1), "r"(a2), "r"(a3), "r"(b0), "r"(b1));
}

// ----------------------------------------------------------------------------
// tf32 GEMM: C[M,N] = A[M,K] @ W[K,N] + bias. M=4096, N=K=1024.
// CTA 128x64, BK=32, 256 threads (8 warps), warp tile 16x64.
// Smem strides: As 36 (banks 4g+t), Bs 72 (banks 8t+g) -> conflict-free frags.
// ----------------------------------------------------------------------------
#define GBM 128
#define GBN 64
#define GBK 32
#define ASTR 36
#define BSTR 72

__global__ __launch_bounds__(256)
void gemm_tf32(const float* __restrict__ A, const float* __restrict__ W,
               const float* __restrict__ bias, float* __restrict__ C) {
    __shared__ uint32_t As[GBM * ASTR];
    __shared__ uint32_t Bs[GBK * BSTR];
    const int tid = threadIdx.x;
    const int w = tid >> 5, lane = tid & 31, g = lane >> 2, t = lane & 3;
    const int bm = blockIdx.y * GBM, bn = blockIdx.x * GBN;
    const int wm = w * 16;

    float acc[8][4] = {};

    float4 pa[4], pb[2];
    // prefetch chunk 0
    #pragma unroll
    for (int r = 0; r < 4; r++) {
        int pos = tid + r * 256, row = pos >> 3, c4 = pos & 7;
        pa[r] = *(const float4*)&A[(size_t)(bm + row) * DM + c4 * 4];
    }
    #pragma unroll
    for (int r = 0; r < 2; r++) {
        int pos = tid + r * 256, row = pos >> 4, c4 = pos & 15;
        pb[r] = *(const float4*)&W[(size_t)row * DM + bn + c4 * 4];
    }

    for (int k0 = 0; k0 < DM; k0 += GBK) {
        #pragma unroll
        for (int r = 0; r < 4; r++) {
            int pos = tid + r * 256, row = pos >> 3, c4 = pos & 7;
            uint32_t* p = &As[row * ASTR + c4 * 4];
            p[0] = f2tf(pa[r].x); p[1] = f2tf(pa[r].y);
            p[2] = f2tf(pa[r].z); p[3] = f2tf(pa[r].w);
        }
        #pragma unroll
        for (int r = 0; r < 2; r++) {
            int pos = tid + r * 256, row = pos >> 4, c4 = pos & 15;
            uint32_t* p = &Bs[row * BSTR + c4 * 4];
            p[0] = f2tf(pb[r].x); p[1] = f2tf(pb[r].y);
            p[2] = f2tf(pb[r].z); p[3] = f2tf(pb[r].w);
        }
        __syncthreads();

        if (k0 + GBK < DM) {
            int kn = k0 + GBK;
            #pragma unroll
            for (int r = 0; r < 4; r++) {
                int pos = tid + r * 256, row = pos >> 3, c4 = pos & 7;
                pa[r] = *(const float4*)&A[(size_t)(bm + row) * DM + kn + c4 * 4];
            }
            #pragma unroll
            for (int r = 0; r < 2; r++) {
                int pos = tid + r * 256, row = pos >> 4, c4 = pos & 15;
                pb[r] = *(const float4*)&W[(size_t)(kn + row) * DM + bn + c4 * 4];
            }
        }

        #pragma unroll
        for (int kk = 0; kk < 4; kk++) {
            int kb = kk * 8;
            uint32_t a0 = As[(wm + g) * ASTR + kb + t];
            uint32_t a1 = As[(wm + g + 8) * ASTR + kb + t];
            uint32_t a2 = As[(wm + g) * ASTR + kb + t + 4];
            uint32_t a3 = As[(wm + g + 8) * ASTR + kb + t + 4];
            #pragma unroll
            for (int nt = 0; nt < 8; nt++) {
                uint32_t b0 = Bs[(kb + t) * BSTR + nt * 8 + g];
                uint32_t b1 = Bs[(kb + t + 4) * BSTR + nt * 8 + g];
                mma_tf32(acc[nt], a0, a1, a2, a3, b0, b1);
            }
        }
        __syncthreads();
    }

    const int row0 = bm + wm + g;
    #pragma unroll
    for (int nt = 0; nt < 8; nt++) {
        int col = bn + nt * 8 + 2 * t;
        float b0v = bias[col], b1v = bias[col + 1];
        float2 v0 = { acc[nt][0] + b0v, acc[nt][1] + b1v };
        *(float2*)&C[(size_t)row0 * DM + col] = v0;
        float2 v1 = { acc[nt][2] + b0v, acc[nt][3] + b1v };
        *(float2*)&C[(size_t)(row0 + 8) * DM + col] = v1;
    }
}

// ----------------------------------------------------------------------------
// tf32 flash attention (causal). CTA = 128 queries of one (b,h); key tiles 64.
// 256 threads = 8 warps, warp = 16 query rows x full 64-key / 64-d tiles.
// Smem: Qs[128][68], Ks[64][68] (key-major), Vs[64][72] (key-major),
//       Ps[128][68] (per-warp P round-trip). All fragment LDS conflict-free.
// ----------------------------------------------------------------------------
#define QSTR 68
#define KSTR 68
#define VSTR 72
#define PSTR 68
#define ATTN_SMEM_WORDS (128*QSTR + 64*KSTR + 64*VSTR + 128*PSTR)

__global__ __launch_bounds__(256)
void attn_tf32(const float* __restrict__ qh, const float* __restrict__ kh,
               const float* __restrict__ vh, float* __restrict__ out) {
    extern __shared__ uint32_t sm[];
    uint32_t* Qs = sm;
    uint32_t* Ks = Qs + 128 * QSTR;
    uint32_t* Vs = Ks + 64 * KSTR;
    uint32_t* Ps = Vs + 64 * VSTR;

    const int tid = threadIdx.x;
    const int w = tid >> 5, lane = tid & 31, g = lane >> 2, t = lane & 3;
    const int qb = blockIdx.x, h = blockIdx.y, bb = blockIdx.z;
    const int q0 = qb * 128, wq = w * 16;

    const float* Qb = qh + (size_t)bb * SEQ * DM + h * HD;
    const float* Kb = kh + (size_t)bb * SEQ * DM + h * HD;
    const float* Vb = vh + (size_t)bb * SEQ * DM + h * HD;

    // Load Q tile, folding softmax scale * log2(e) so we can use exp2.
    const float QSCALE = 0.125f * 1.44269504088896f;
    #pragma unroll
    for (int r = 0; r < 8; r++) {
        int pos = tid + r * 256, row = pos >> 4, d4 = pos & 15;
        float4 v = *(const float4*)&Qb[(size_t)(q0 + row) * DM + d4 * 4];
        uint32_t* p = &Qs[row * QSTR + d4 * 4];
        p[0] = f2tf(v.x * QSCALE); p[1] = f2tf(v.y * QSCALE);
        p[2] = f2tf(v.z * QSCALE); p[3] = f2tf(v.w * QSCALE);
    }

    float ofr[8][4] = {};
    float m0 = -1e30f, m1 = -1e30f, l0 = 0.f, l1 = 0.f;

    const int ntiles = 2 * qb + 2;
    float4 pk[4], pv[4];
    #pragma unroll
    for (int r = 0; r < 4; r++) {
        int pos = tid + r * 256, key = pos >> 4, d4 = pos & 15;
        pk[r] = *(const float4*)&Kb[(size_t)key * DM + d4 * 4];
        pv[r] = *(const float4*)&Vb[(size_t)key * DM + d4 * 4];
    }

    uint32_t* Pw = Ps + wq * PSTR;

    for (int jt = 0; jt < ntiles; jt++) {
        const int j0 = jt * 64;
        __syncthreads();   // prior tile's reads done (and Q store on iter 0)
        #pragma unroll
        for (int r = 0; r < 4; r++) {
            int pos = tid + r * 256, key = pos >> 4, d4 = pos & 15;
            uint32_t* p = &Ks[key * KSTR + d4 * 4];
            p[0] = f2tf(pk[r].x); p[1] = f2tf(pk[r].y);
            p[2] = f2tf(pk[r].z); p[3] = f2tf(pk[r].w);
            uint32_t* q = &Vs[key * VSTR + d4 * 4];
            q[0] = f2tf(pv[r].x); q[1] = f2tf(pv[r].y);
            q[2] = f2tf(pv[r].z); q[3] = f2tf(pv[r].w);
        }
        __syncthreads();

        if (jt + 1 < ntiles) {
            int jn = j0 + 64;
            #pragma unroll
            for (int r = 0; r < 4; r++) {
                int pos = tid + r * 256, key = pos >> 4, d4 = pos & 15;
                pk[r] = *(const float4*)&Kb[(size_t)(jn + key) * DM + d4 * 4];
                pv[r] = *(const float4*)&Vb[(size_t)(jn + key) * DM + d4 * 4];
            }
        }

        // S = Q K^T  (B frag reads K^T from key-major Ks)
        float s[8][4] = {};
        #pragma unroll
        for (int kk = 0; kk < 8; kk++) {
            int kb = kk * 8;
            uint32_t a0 = Qs[(wq + g) * QSTR + kb + t];
            uint32_t a1 = Qs[(wq + g + 8) * QSTR + kb + t];
            uint32_t a2 = Qs[(wq + g) * QSTR + kb + t + 4];
            uint32_t a3 = Qs[(wq + g + 8) * QSTR + kb + t + 4];
            #pragma unroll
            for (int nt = 0; nt < 8; nt++) {
                uint32_t b0 = Ks[(nt * 8 + g) * KSTR + kb + t];
                uint32_t b1 = Ks[(nt * 8 + g) * KSTR + kb + t + 4];
                mma_tf32(s[nt], a0, a1, a2, a3, b0, b1);
            }
        }

        // causal mask (only tiles that cross the warp's diagonal)
        if (j0 + 63 > q0 + wq) {
            int r0 = q0 + wq + g, r1 = r0 + 8;
            #pragma unroll
            for (int nt = 0; nt < 8; nt++) {
                int key = j0 + nt * 8 + 2 * t;
                if (key > r0)     s[nt][0] = -1e30f;
                if (key + 1 > r0) s[nt][1] = -1e30f;
                if (key > r1)     s[nt][2] = -1e30f;
                if (key + 1 > r1) s[nt][3] = -1e30f;
            }
        }

        // online softmax (base 2; scale folded into Q)
        float tm0 = -1e30f, tm1 = -1e30f;
        #pragma unroll
        for (int nt = 0; nt < 8; nt++) {
            tm0 = fmaxf(tm0, fmaxf(s[nt][0], s[nt][1]));
            tm1 = fmaxf(tm1, fmaxf(s[nt][2], s[nt][3]));
        }
        tm0 = fmaxf(tm0, __shfl_xor_sync(0xffffffffu, tm0, 1));
        tm0 = fmaxf(tm0, __shfl_xor_sync(0xffffffffu, tm0, 2));
        tm1 = fmaxf(tm1, __shfl_xor_sync(0xffffffffu, tm1, 1));
        tm1 = fmaxf(tm1, __shfl_xor_sync(0xffffffffu, tm1, 2));

        float nm0 = fmaxf(m0, tm0), nm1 = fmaxf(m1, tm1);
        float al0 = exp2f(m0 - nm0), al1 = exp2f(m1 - nm1);
        m0 = nm0; m1 = nm1;

        float rs0 = 0.f, rs1 = 0.f;
        #pragma unroll
        for (int nt = 0; nt < 8; nt++) {
            s[nt][0] = exp2f(s[nt][0] - nm0); rs0 += s[nt][0];
            s[nt][1] = exp2f(s[nt][1] - nm0); rs0 += s[nt][1];
            s[nt][2] = exp2f(s[nt][2] - nm1); rs1 += s[nt][2];
            s[nt][3] = exp2f(s[nt][3] - nm1); rs1 += s[nt][3];
        }
        rs0 += __shfl_xor_sync(0xffffffffu, rs0, 1);
        rs0 += __shfl_xor_sync(0xffffffffu, rs0, 2);
        rs1 += __shfl_xor_sync(0xffffffffu, rs1, 1);
        rs1 += __shfl_xor_sync(0xffffffffu, rs1, 2);
        l0 = l0 * al0 + rs0;
        l1 = l1 * al1 + rs1;

        #pragma unroll
        for (int nt = 0; nt < 8; nt++) {
            ofr[nt][0] *= al0; ofr[nt][1] *= al0;
            ofr[nt][2] *= al1; ofr[nt][3] *= al1;
        }

        // P -> per-warp smem (C-frag layout -> A-frag layout round trip)
        #pragma unroll
        for (int nt = 0; nt < 8; nt++) {
            int c = nt * 8 + 2 * t;
            Pw[g * PSTR + c]           = f2tf(s[nt][0]);
            Pw[g * PSTR + c + 1]       = f2tf(s[nt][1]);
            Pw[(g + 8) * PSTR + c]     = f2tf(s[nt][2]);
            Pw[(g + 8) * PSTR + c + 1] = f2tf(s[nt][3]);
        }
        __syncwarp();

        // O += P @ V
        #pragma unroll
        for (int kk = 0; kk < 8; kk++) {
            int kb = kk * 8;
            uint32_t a0 = Pw[g * PSTR + kb + t];
            uint32_t a1 = Pw[(g + 8) * PSTR + kb + t];
            uint32_t a2 = Pw[g * PSTR + kb + t + 4];
            uint32_t a3 = Pw[(g + 8) * PSTR + kb + t + 4];
            #pragma unroll
            for (int nt = 0; nt < 8; nt++) {
                uint32_t b0 = Vs[(kb + t) * VSTR + nt * 8 + g];
                uint32_t b1 = Vs[(kb + t + 4) * VSTR + nt * 8 + g];
                mma_tf32(ofr[nt], a0, a1, a2, a3, b0, b1);
            }
        }
    }

    const float inv0 = 1.f / l0, inv1 = 1.f / l1;
    const int row0 = q0 + wq + g;
    #pragma unroll
    for (int nt = 0; nt < 8; nt++) {
        int col = h * HD + nt * 8 + 2 * t;
        float2 v0 = { ofr[nt][0] * inv0, ofr[nt][1] * inv0 };
        *(float2*)&out[((size_t)bb * SEQ + row0) * DM + col] = v0;
        float2 v1 = { ofr[nt][2] * inv1, ofr[nt][3] * inv1 };
        *(float2*)&out[((size_t)bb * SEQ + row0 + 8) * DM + col] = v1;
    }
}

// ----------------------------------------------------------------------------
extern "C" void kernel_launch(void* const* d_in, const int* in_sizes, int n_in,
                              void* d_out, int out_size) {
    const float* q  = (const float*)d_in[0];
    const float* k  = (const float*)d_in[1];
    const float* v  = (const float*)d_in[2];
    const float* Wq = (const float*)d_in[3];
    const float* bq = (const float*)d_in[4];
    const float* Wk = (const float*)d_in[5];
    const float* bk = (const float*)d_in[6];
    const float* Wv = (const float*)d_in[7];
    const float* bv = (const float*)d_in[8];
    const float* Wo = (const float*)d_in[9];
    const float* bo = (const float*)d_in[10];
    float* out = (float*)d_out;

    float *qh, *khp, *vhp, *ao;
    cudaGetSymbolAddress((void**)&qh,  g_qh);
    cudaGetSymbolAddress((void**)&khp, g_kh);
    cudaGetSymbolAddress((void**)&vhp, g_vh);
    cudaGetSymbolAddress((void**)&ao,  g_ao);

    dim3 ggrid(DM / GBN, MTOT / GBM);
    gemm_tf32<<<ggrid, 256>>>(q, Wq, bq, qh);
    gemm_tf32<<<ggrid, 256>>>(k, Wk, bk, khp);
    gemm_tf32<<<ggrid, 256>>>(v, Wv, bv, vhp);

    size_t smem = ATTN_SMEM_WORDS * sizeof(uint32_t);  // 105,472 B
    cudaFuncSetAttribute(attn_tf32, cudaFuncAttributeMaxDynamicSharedMemorySize,
                         (int)smem);
    attn_tf32<<<dim3(SEQ / 128, NH, BATCH), 256, smem>>>(qh, khp, vhp, ao);

    gemm_tf32<<<ggrid, 256>>>(ao, Wo, bo, out);
}

// round 6
// speedup vs baseline: 5.0552x; 1.6934x over previous
#include <cuda_runtime.h>
#include <cuda_fp16.h>
#include <math.h>
#include <stdint.h>

#define BATCH 2
#define SEQ   2048
#define DM    1024
#define NH    16
#define HD    64
#define MTOT  (BATCH*SEQ)   // 4096

// ---------------- scratch (allocation-free) ----------------
__device__ __half g_ah[MTOT * DM];   // fp16 GEMM activation input
__device__ __half g_wt[DM * DM];     // fp16 W^T [N][K]
__device__ __half g_qh[MTOT * DM];   // projected Q (pre-scaled), fp16
__device__ __half g_kh[MTOT * DM];
__device__ __half g_vh[MTOT * DM];
__device__ __half g_ao[MTOT * DM];   // attention output, fp16

// fp16 mma m16n8k16, fp32 accum
__device__ __forceinline__ void mma_f16(float d[4],
    uint32_t a0, uint32_t a1, uint32_t a2, uint32_t a3,
    uint32_t b0, uint32_t b1) {
    asm volatile(
        "mma.sync.aligned.m16n8k16.row.col.f32.f16.f16.f32 "
        "{%0,%1,%2,%3}, {%4,%5,%6,%7}, {%8,%9}, {%0,%1,%2,%3};\n"
        : "+f"(d[0]), "+f"(d[1]), "+f"(d[2]), "+f"(d[3])
        : "r"(a0), "r"(a1), "r"(a2), "r"(a3), "r"(b0), "r"(b1));
}

// ---------------- prep kernels ----------------
__global__ __launch_bounds__(256)
void conv_half(const float* __restrict__ in, __half* __restrict__ out, int n8) {
    int i = blockIdx.x * 256 + threadIdx.x;
    if (i >= n8) return;
    float4 v0 = ((const float4*)in)[2 * i];
    float4 v1 = ((const float4*)in)[2 * i + 1];
    __half2 p0 = __floats2half2_rn(v0.x, v0.y);
    __half2 p1 = __floats2half2_rn(v0.z, v0.w);
    __half2 p2 = __floats2half2_rn(v1.x, v1.y);
    __half2 p3 = __floats2half2_rn(v1.z, v1.w);
    uint4 o;
    o.x = *(uint32_t*)&p0; o.y = *(uint32_t*)&p1;
    o.z = *(uint32_t*)&p2; o.w = *(uint32_t*)&p3;
    ((uint4*)out)[i] = o;
}

// W[K][N] fp32 -> Wt[N][K] fp16 (scaled)
__global__ __launch_bounds__(256)
void transpose_half(const float* __restrict__ W, __half* __restrict__ Wt, float scale) {
    __shared__ float tile[32][33];
    const int k0 = blockIdx.x * 32, n0 = blockIdx.y * 32;
    const int tx = threadIdx.x, ty = threadIdx.y;   // 32 x 8
    #pragma unroll
    for (int r = 0; r < 4; r++)
        tile[ty + 8 * r][tx] = W[(size_t)(k0 + ty + 8 * r) * DM + n0 + tx];
    __syncthreads();
    #pragma unroll
    for (int r = 0; r < 4; r++)
        Wt[(size_t)(n0 + ty + 8 * r) * DM + k0 + tx] =
            __float2half_rn(tile[tx][ty + 8 * r] * scale);
}

// ---------------- fp16 GEMM ----------------
// C = A[M,K] @ Wt^T + bias*bscale.  CTA 128x128, BK=32, 8 warps (4x2), warp 32x64.
#define GSTR 20   // u32 per row (40 halves, conflict-free: g*20 mod 32 is a permutation)

__global__ __launch_bounds__(256, 2)
void gemm_h(const __half* __restrict__ A, const __half* __restrict__ Wt,
            const float* __restrict__ bias, float bscale,
            float* __restrict__ Cf, __half* __restrict__ Ch) {
    __shared__ uint32_t As[128 * GSTR];
    __shared__ uint32_t Bs[128 * GSTR];
    const int tid = threadIdx.x;
    const int wid = tid >> 5, lane = tid & 31, g = lane >> 2, t = lane & 3;
    const int n0 = blockIdx.x * 128, m0 = blockIdx.y * 128;
    const int wm = (wid >> 1) * 32, wn = (wid & 1) * 64;

    float acc[16][4] = {};
    uint4 pa[2], pb[2];

    #pragma unroll
    for (int it = 0; it < 2; it++) {
        int idx = tid + it * 256, row = idx >> 2, c = idx & 3;
        pa[it] = *(const uint4*)&A[(size_t)(m0 + row) * DM + c * 8];
        pb[it] = *(const uint4*)&Wt[(size_t)(n0 + row) * DM + c * 8];
    }

    for (int k0 = 0; k0 < DM; k0 += 32) {
        __syncthreads();
        #pragma unroll
        for (int it = 0; it < 2; it++) {
            int idx = tid + it * 256, row = idx >> 2, c = idx & 3;
            *(uint4*)&As[row * GSTR + c * 4] = pa[it];
            *(uint4*)&Bs[row * GSTR + c * 4] = pb[it];
        }
        __syncthreads();

        if (k0 + 32 < DM) {
            int kn = k0 + 32;
            #pragma unroll
            for (int it = 0; it < 2; it++) {
                int idx = tid + it * 256, row = idx >> 2, c = idx & 3;
                pa[it] = *(const uint4*)&A[(size_t)(m0 + row) * DM + kn + c * 8];
                pb[it] = *(const uint4*)&Wt[(size_t)(n0 + row) * DM + kn + c * 8];
            }
        }

        #pragma unroll
        for (int kk = 0; kk < 2; kk++) {
            uint32_t af[2][4], bf[8][2];
            #pragma unroll
            for (int mt = 0; mt < 2; mt++) {
                int r = wm + mt * 16 + g;
                af[mt][0] = As[r * GSTR + kk * 8 + t];
                af[mt][1] = As[(r + 8) * GSTR + kk * 8 + t];
                af[mt][2] = As[r * GSTR + kk * 8 + t + 4];
                af[mt][3] = As[(r + 8) * GSTR + kk * 8 + t + 4];
            }
            #pragma unroll
            for (int nt = 0; nt < 8; nt++) {
                int r = wn + nt * 8 + g;
                bf[nt][0] = Bs[r * GSTR + kk * 8 + t];
                bf[nt][1] = Bs[r * GSTR + kk * 8 + t + 4];
            }
            #pragma unroll
            for (int mt = 0; mt < 2; mt++)
                #pragma unroll
                for (int nt = 0; nt < 8; nt++)
                    mma_f16(acc[mt * 8 + nt], af[mt][0], af[mt][1], af[mt][2], af[mt][3],
                            bf[nt][0], bf[nt][1]);
        }
    }

    #pragma unroll
    for (int mt = 0; mt < 2; mt++) {
        int row = m0 + wm + mt * 16 + g;
        #pragma unroll
        for (int nt = 0; nt < 8; nt++) {
            int col = n0 + wn + nt * 8 + 2 * t;
            float b0 = bias[col] * bscale, b1 = bias[col + 1] * bscale;
            float* a = acc[mt * 8 + nt];
            float v00 = a[0] + b0, v01 = a[1] + b1;
            float v10 = a[2] + b0, v11 = a[3] + b1;
            if (Cf) {
                float2 x0 = { v00, v01 };
                *(float2*)&Cf[(size_t)row * DM + col] = x0;
                float2 x1 = { v10, v11 };
                *(float2*)&Cf[(size_t)(row + 8) * DM + col] = x1;
            }
            if (Ch) {
                __half2 h0 = __floats2half2_rn(v00, v01);
                *(uint32_t*)&Ch[(size_t)row * DM + col] = *(uint32_t*)&h0;
                __half2 h1 = __floats2half2_rn(v10, v11);
                *(uint32_t*)&Ch[(size_t)(row + 8) * DM + col] = *(uint32_t*)&h1;
            }
        }
    }
}

// ---------------- fp16 flash attention (causal) ----------------
// CTA = 128 queries of one (b,h); 8 warps, warp = 16 queries x 64 keys.
// Q pre-scaled by 0.125*log2(e) (folded into Wq/bq). P stays in registers:
// S C-frag packed to half2 IS the A-frag of the PV mma.
#define AQ 36   // u32 stride (72 halves); g*4 mod 32 permutation -> conflict-free

__global__ __launch_bounds__(256, 2)
void attn_h(const __half* __restrict__ qh, const __half* __restrict__ kh,
            const __half* __restrict__ vh, __half* __restrict__ out) {
    __shared__ uint32_t Qs[128 * AQ];
    __shared__ uint32_t Ks[64 * AQ];
    __shared__ uint32_t Vt[64 * AQ];   // V^T: [d][key]

    const int tid = threadIdx.x;
    const int w = tid >> 5, lane = tid & 31, g = lane >> 2, t = lane & 3;
    const int qb = blockIdx.x, h = blockIdx.y, bb = blockIdx.z;
    const int q0 = qb * 128, wq = w * 16;

    const __half* Qb = qh + (size_t)bb * SEQ * DM + h * HD;
    const __half* Kb = kh + (size_t)bb * SEQ * DM + h * HD;
    const __half* Vb = vh + (size_t)bb * SEQ * DM + h * HD;

    #pragma unroll
    for (int r = 0; r < 4; r++) {
        int idx = tid + r * 256, row = idx >> 3, c = idx & 7;
        uint4 v = *(const uint4*)&Qb[(size_t)(q0 + row) * DM + c * 8];
        *(uint4*)&Qs[row * AQ + c * 4] = v;
    }

    float ofr[8][4] = {};
    float m0 = -1e30f, m1 = -1e30f, l0 = 0.f, l1 = 0.f;
    const int ntiles = 2 * qb + 2;
    const int kp = tid & 31, dg = tid >> 5;

    uint4 pk[2], pva, pvb;
    #pragma unroll
    for (int r = 0; r < 2; r++) {
        int idx = tid + r * 256, row = idx >> 3, c = idx & 7;
        pk[r] = *(const uint4*)&Kb[(size_t)row * DM + c * 8];
    }
    pva = *(const uint4*)&Vb[(size_t)(2 * kp) * DM + dg * 8];
    pvb = *(const uint4*)&Vb[(size_t)(2 * kp + 1) * DM + dg * 8];

    for (int jt = 0; jt < ntiles; jt++) {
        const int j0 = jt * 64;
        __syncthreads();   // prior tile's reads done (and Q store on iter 0)
        #pragma unroll
        for (int r = 0; r < 2; r++) {
            int idx = tid + r * 256, row = idx >> 3, c = idx & 7;
            *(uint4*)&Ks[row * AQ + c * 4] = pk[r];
        }
        {
            __half ha[8], hb[8];
            *(uint4*)ha = pva;
            *(uint4*)hb = pvb;
            #pragma unroll
            for (int j = 0; j < 8; j++) {
                __half2 p = __halves2half2(ha[j], hb[j]);   // low = even key
                Vt[(dg * 8 + j) * AQ + kp] = *(uint32_t*)&p;
            }
        }
        __syncthreads();

        if (jt + 1 < ntiles) {
            int jn = j0 + 64;
            #pragma unroll
            for (int r = 0; r < 2; r++) {
                int idx = tid + r * 256, row = idx >> 3, c = idx & 7;
                pk[r] = *(const uint4*)&Kb[(size_t)(jn + row) * DM + c * 8];
            }
            pva = *(const uint4*)&Vb[(size_t)(jn + 2 * kp) * DM + dg * 8];
            pvb = *(const uint4*)&Vb[(size_t)(jn + 2 * kp + 1) * DM + dg * 8];
        }

        // S = Q K^T
        float s[8][4] = {};
        #pragma unroll
        for (int kk = 0; kk < 4; kk++) {
            uint32_t a0 = Qs[(wq + g) * AQ + kk * 8 + t];
            uint32_t a1 = Qs[(wq + g + 8) * AQ + kk * 8 + t];
            uint32_t a2 = Qs[(wq + g) * AQ + kk * 8 + t + 4];
            uint32_t a3 = Qs[(wq + g + 8) * AQ + kk * 8 + t + 4];
            #pragma unroll
            for (int nt = 0; nt < 8; nt++) {
                uint32_t b0 = Ks[(nt * 8 + g) * AQ + kk * 8 + t];
                uint32_t b1 = Ks[(nt * 8 + g) * AQ + kk * 8 + t + 4];
                mma_f16(s[nt], a0, a1, a2, a3, b0, b1);
            }
        }

        // causal mask
        if (j0 + 63 > q0 + wq) {
            int r0 = q0 + wq + g, r1 = r0 + 8;
            #pragma unroll
            for (int nt = 0; nt < 8; nt++) {
                int key = j0 + nt * 8 + 2 * t;
                if (key > r0)     s[nt][0] = -1e30f;
                if (key + 1 > r0) s[nt][1] = -1e30f;
                if (key > r1)     s[nt][2] = -1e30f;
                if (key + 1 > r1) s[nt][3] = -1e30f;
            }
        }

        // online softmax (base-2; scale folded into Wq/bq)
        float tm0 = -1e30f, tm1 = -1e30f;
        #pragma unroll
        for (int nt = 0; nt < 8; nt++) {
            tm0 = fmaxf(tm0, fmaxf(s[nt][0], s[nt][1]));
            tm1 = fmaxf(tm1, fmaxf(s[nt][2], s[nt][3]));
        }
        tm0 = fmaxf(tm0, __shfl_xor_sync(0xffffffffu, tm0, 1));
        tm0 = fmaxf(tm0, __shfl_xor_sync(0xffffffffu, tm0, 2));
        tm1 = fmaxf(tm1, __shfl_xor_sync(0xffffffffu, tm1, 1));
        tm1 = fmaxf(tm1, __shfl_xor_sync(0xffffffffu, tm1, 2));

        float nm0 = fmaxf(m0, tm0), nm1 = fmaxf(m1, tm1);
        float al0 = exp2f(m0 - nm0), al1 = exp2f(m1 - nm1);
        m0 = nm0; m1 = nm1;

        float rs0 = 0.f, rs1 = 0.f;
        #pragma unroll
        for (int nt = 0; nt < 8; nt++) {
            s[nt][0] = exp2f(s[nt][0] - nm0); rs0 += s[nt][0];
            s[nt][1] = exp2f(s[nt][1] - nm0); rs0 += s[nt][1];
            s[nt][2] = exp2f(s[nt][2] - nm1); rs1 += s[nt][2];
            s[nt][3] = exp2f(s[nt][3] - nm1); rs1 += s[nt][3];
        }
        rs0 += __shfl_xor_sync(0xffffffffu, rs0, 1);
        rs0 += __shfl_xor_sync(0xffffffffu, rs0, 2);
        rs1 += __shfl_xor_sync(0xffffffffu, rs1, 1);
        rs1 += __shfl_xor_sync(0xffffffffu, rs1, 2);
        l0 = l0 * al0 + rs0;
        l1 = l1 * al1 + rs1;

        #pragma unroll
        for (int nt = 0; nt < 8; nt++) {
            ofr[nt][0] *= al0; ofr[nt][1] *= al0;
            ofr[nt][2] *= al1; ofr[nt][3] *= al1;
        }

        // P C-frag -> half2 A-frag, directly into PV mma (no smem round trip)
        #pragma unroll
        for (int c = 0; c < 4; c++) {
            __half2 h0 = __floats2half2_rn(s[2 * c][0], s[2 * c][1]);
            __half2 h1 = __floats2half2_rn(s[2 * c][2], s[2 * c][3]);
            __half2 h2 = __floats2half2_rn(s[2 * c + 1][0], s[2 * c + 1][1]);
            __half2 h3 = __floats2half2_rn(s[2 * c + 1][2], s[2 * c + 1][3]);
            uint32_t pa0 = *(uint32_t*)&h0, pa1 = *(uint32_t*)&h1;
            uint32_t pa2 = *(uint32_t*)&h2, pa3 = *(uint32_t*)&h3;
            #pragma unroll
            for (int dt = 0; dt < 8; dt++) {
                uint32_t b0 = Vt[(dt * 8 + g) * AQ + c * 8 + t];
                uint32_t b1 = Vt[(dt * 8 + g) * AQ + c * 8 + t + 4];
                mma_f16(ofr[dt], pa0, pa1, pa2, pa3, b0, b1);
            }
        }
    }

    const float inv0 = 1.f / l0, inv1 = 1.f / l1;
    const int row0 = q0 + wq + g;
    #pragma unroll
    for (int dt = 0; dt < 8; dt++) {
        int col = h * HD + dt * 8 + 2 * t;
        __half2 v0 = __floats2half2_rn(ofr[dt][0] * inv0, ofr[dt][1] * inv0);
        *(uint32_t*)&out[((size_t)bb * SEQ + row0) * DM + col] = *(uint32_t*)&v0;
        __half2 v1 = __floats2half2_rn(ofr[dt][2] * inv1, ofr[dt][3] * inv1);
        *(uint32_t*)&out[((size_t)bb * SEQ + row0 + 8) * DM + col] = *(uint32_t*)&v1;
    }
}

// ----------------------------------------------------------------------------
extern "C" void kernel_launch(void* const* d_in, const int* in_sizes, int n_in,
                              void* d_out, int out_size) {
    const float* q  = (const float*)d_in[0];
    const float* k  = (const float*)d_in[1];
    const float* v  = (const float*)d_in[2];
    const float* Wq = (const float*)d_in[3];
    const float* bq = (const float*)d_in[4];
    const float* Wk = (const float*)d_in[5];
    const float* bk = (const float*)d_in[6];
    const float* Wv = (const float*)d_in[7];
    const float* bv = (const float*)d_in[8];
    const float* Wo = (const float*)d_in[9];
    const float* bo = (const float*)d_in[10];
    float* out = (float*)d_out;

    __half *ah, *wt, *qh, *kh, *vh, *ao;
    cudaGetSymbolAddress((void**)&ah, g_ah);
    cudaGetSymbolAddress((void**)&wt, g_wt);
    cudaGetSymbolAddress((void**)&qh, g_qh);
    cudaGetSymbolAddress((void**)&kh, g_kh);
    cudaGetSymbolAddress((void**)&vh, g_vh);
    cudaGetSymbolAddress((void**)&ao, g_ao);

    const float QSCALE = 0.125f * 1.44269504088896f;  // 1/sqrt(64) * log2(e)
    const int n8 = MTOT * DM / 8;
    const dim3 tgrid(DM / 32, DM / 32), tblk(32, 8);
    const dim3 ggrid(DM / 128, MTOT / 128);   // (8, 32)

    conv_half<<<n8 / 256, 256>>>(q, ah, n8);
    transpose_half<<<tgrid, tblk>>>(Wq, wt, QSCALE);
    gemm_h<<<ggrid, 256>>>(ah, wt, bq, QSCALE, nullptr, qh);

    conv_half<<<n8 / 256, 256>>>(k, ah, n8);
    transpose_half<<<tgrid, tblk>>>(Wk, wt, 1.f);
    gemm_h<<<ggrid, 256>>>(ah, wt, bk, 1.f, nullptr, kh);

    conv_half<<<n8 / 256, 256>>>(v, ah, n8);
    transpose_half<<<tgrid, tblk>>>(Wv, wt, 1.f);
    gemm_h<<<ggrid, 256>>>(ah, wt, bv, 1.f, nullptr, vh);

    attn_h<<<dim3(SEQ / 128, NH, BATCH), 256>>>(qh, kh, vh, ao);

    transpose_half<<<tgrid, tblk>>>(Wo, wt, 1.f);
    gemm_h<<<ggrid, 256>>>(ao, wt, bo, 1.f, out, nullptr);
}

// round 7
// speedup vs baseline: 5.4541x; 1.0789x over previous
#include <cuda_runtime.h>
#include <cuda_fp16.h>
#include <math.h>
#include <stdint.h>

#define BATCH 2
#define SEQ   2048
#define DM    1024
#define NH    16
#define HD    64
#define MTOT  (BATCH*SEQ)   // 4096

// ---------------- scratch (allocation-free) ----------------
__device__ __half g_aq[MTOT * DM];   // fp16 activations (q,k,v)
__device__ __half g_ak[MTOT * DM];
__device__ __half g_av[MTOT * DM];
__device__ __half g_wt0[DM * DM];    // fp16 W^T buffers
__device__ __half g_wt1[DM * DM];
__device__ __half g_wt2[DM * DM];
__device__ __half g_wto[DM * DM];
__device__ __half g_qh[MTOT * DM];   // projected Q (pre-scaled)
__device__ __half g_kh[MTOT * DM];
__device__ __half g_vh[MTOT * DM];
__device__ __half g_ao[MTOT * DM];   // attention output

// fp16 mma m16n8k16, fp32 accum
__device__ __forceinline__ void mma_f16(float d[4],
    uint32_t a0, uint32_t a1, uint32_t a2, uint32_t a3,
    uint32_t b0, uint32_t b1) {
    asm volatile(
        "mma.sync.aligned.m16n8k16.row.col.f32.f16.f16.f32 "
        "{%0,%1,%2,%3}, {%4,%5,%6,%7}, {%8,%9}, {%0,%1,%2,%3};\n"
        : "+f"(d[0]), "+f"(d[1]), "+f"(d[2]), "+f"(d[3])
        : "r"(a0), "r"(a1), "r"(a2), "r"(a3), "r"(b0), "r"(b1));
}

// ---------------- prep kernels ----------------
__global__ __launch_bounds__(256)
void conv3(const float* __restrict__ q, const float* __restrict__ k,
           const float* __restrict__ v, __half* __restrict__ oq,
           __half* __restrict__ ok, __half* __restrict__ ov, int n8) {
    int i = blockIdx.x * 256 + threadIdx.x;
    if (i >= n8) return;
    const float* in = (blockIdx.y == 0) ? q : (blockIdx.y == 1) ? k : v;
    __half* out = (blockIdx.y == 0) ? oq : (blockIdx.y == 1) ? ok : ov;
    float4 v0 = ((const float4*)in)[2 * i];
    float4 v1 = ((const float4*)in)[2 * i + 1];
    __half2 p0 = __floats2half2_rn(v0.x, v0.y);
    __half2 p1 = __floats2half2_rn(v0.z, v0.w);
    __half2 p2 = __floats2half2_rn(v1.x, v1.y);
    __half2 p3 = __floats2half2_rn(v1.z, v1.w);
    uint4 o;
    o.x = *(uint32_t*)&p0; o.y = *(uint32_t*)&p1;
    o.z = *(uint32_t*)&p2; o.w = *(uint32_t*)&p3;
    ((uint4*)out)[i] = o;
}

// W[K][N] fp32 -> Wt[N][K] fp16 (scale on z==0 only when qs != 1)
__device__ __forceinline__ void transpose_body(const float* __restrict__ W,
                                               __half* __restrict__ Wt, float scale) {
    __shared__ float tile[32][33];
    const int k0 = blockIdx.x * 32, n0 = blockIdx.y * 32;
    const int tx = threadIdx.x, ty = threadIdx.y;   // 32 x 8
    #pragma unroll
    for (int r = 0; r < 4; r++)
        tile[ty + 8 * r][tx] = W[(size_t)(k0 + ty + 8 * r) * DM + n0 + tx];
    __syncthreads();
    #pragma unroll
    for (int r = 0; r < 4; r++)
        Wt[(size_t)(n0 + ty + 8 * r) * DM + k0 + tx] =
            __float2half_rn(tile[tx][ty + 8 * r] * scale);
}

__global__ __launch_bounds__(256)
void trans3(const float* __restrict__ W0, const float* __restrict__ W1,
            const float* __restrict__ W2, __half* __restrict__ T0,
            __half* __restrict__ T1, __half* __restrict__ T2, float qs) {
    const int z = blockIdx.z;
    const float* W = (z == 0) ? W0 : (z == 1) ? W1 : W2;
    __half* T = (z == 0) ? T0 : (z == 1) ? T1 : T2;
    transpose_body(W, T, (z == 0) ? qs : 1.f);
}

__global__ __launch_bounds__(256)
void trans1(const float* __restrict__ W, __half* __restrict__ T) {
    transpose_body(W, T, 1.f);
}

// ---------------- fp16 GEMM body ----------------
// C = A[M,K] @ Wt^T + bias*bscale.  CTA 128x128, BK=32, 8 warps (4x2), warp 32x64.
#define GSTR 20   // u32 per row (40 halves, conflict-free)

__device__ __forceinline__ void gemm_body(const __half* __restrict__ A,
        const __half* __restrict__ Wt, const float* __restrict__ bias, float bscale,
        float* __restrict__ Cf, __half* __restrict__ Ch) {
    __shared__ uint32_t As[128 * GSTR];
    __shared__ uint32_t Bs[128 * GSTR];
    const int tid = threadIdx.x;
    const int wid = tid >> 5, lane = tid & 31, g = lane >> 2, t = lane & 3;
    const int n0 = blockIdx.x * 128, m0 = blockIdx.y * 128;
    const int wm = (wid >> 1) * 32, wn = (wid & 1) * 64;

    float acc[16][4] = {};
    uint4 pa[2], pb[2];

    #pragma unroll
    for (int it = 0; it < 2; it++) {
        int idx = tid + it * 256, row = idx >> 2, c = idx & 3;
        pa[it] = *(const uint4*)&A[(size_t)(m0 + row) * DM + c * 8];
        pb[it] = *(const uint4*)&Wt[(size_t)(n0 + row) * DM + c * 8];
    }

    for (int k0 = 0; k0 < DM; k0 += 32) {
        __syncthreads();
        #pragma unroll
        for (int it = 0; it < 2; it++) {
            int idx = tid + it * 256, row = idx >> 2, c = idx & 3;
            *(uint4*)&As[row * GSTR + c * 4] = pa[it];
            *(uint4*)&Bs[row * GSTR + c * 4] = pb[it];
        }
        __syncthreads();

        if (k0 + 32 < DM) {
            int kn = k0 + 32;
            #pragma unroll
            for (int it = 0; it < 2; it++) {
                int idx = tid + it * 256, row = idx >> 2, c = idx & 3;
                pa[it] = *(const uint4*)&A[(size_t)(m0 + row) * DM + kn + c * 8];
                pb[it] = *(const uint4*)&Wt[(size_t)(n0 + row) * DM + kn + c * 8];
            }
        }

        #pragma unroll
        for (int kk = 0; kk < 2; kk++) {
            uint32_t af[2][4], bf[8][2];
            #pragma unroll
            for (int mt = 0; mt < 2; mt++) {
                int r = wm + mt * 16 + g;
                af[mt][0] = As[r * GSTR + kk * 8 + t];
                af[mt][1] = As[(r + 8) * GSTR + kk * 8 + t];
                af[mt][2] = As[r * GSTR + kk * 8 + t + 4];
                af[mt][3] = As[(r + 8) * GSTR + kk * 8 + t + 4];
            }
            #pragma unroll
            for (int nt = 0; nt < 8; nt++) {
                int r = wn + nt * 8 + g;
                bf[nt][0] = Bs[r * GSTR + kk * 8 + t];
                bf[nt][1] = Bs[r * GSTR + kk * 8 + t + 4];
            }
            #pragma unroll
            for (int mt = 0; mt < 2; mt++)
                #pragma unroll
                for (int nt = 0; nt < 8; nt++)
                    mma_f16(acc[mt * 8 + nt], af[mt][0], af[mt][1], af[mt][2], af[mt][3],
                            bf[nt][0], bf[nt][1]);
        }
    }

    #pragma unroll
    for (int mt = 0; mt < 2; mt++) {
        int row = m0 + wm + mt * 16 + g;
        #pragma unroll
        for (int nt = 0; nt < 8; nt++) {
            int col = n0 + wn + nt * 8 + 2 * t;
            float b0 = bias[col] * bscale, b1 = bias[col + 1] * bscale;
            float* a = acc[mt * 8 + nt];
            float v00 = a[0] + b0, v01 = a[1] + b1;
            float v10 = a[2] + b0, v11 = a[3] + b1;
            if (Cf) {
                float2 x0 = { v00, v01 };
                *(float2*)&Cf[(size_t)row * DM + col] = x0;
                float2 x1 = { v10, v11 };
                *(float2*)&Cf[(size_t)(row + 8) * DM + col] = x1;
            }
            if (Ch) {
                __half2 h0 = __floats2half2_rn(v00, v01);
                *(uint32_t*)&Ch[(size_t)row * DM + col] = *(uint32_t*)&h0;
                __half2 h1 = __floats2half2_rn(v10, v11);
                *(uint32_t*)&Ch[(size_t)(row + 8) * DM + col] = *(uint32_t*)&h1;
            }
        }
    }
}

// fused QKV projection GEMM (z selects chain)
__global__ __launch_bounds__(256, 2)
void gemm3(const __half* __restrict__ aq, const __half* __restrict__ ak,
           const __half* __restrict__ av, const __half* __restrict__ w0,
           const __half* __restrict__ w1, const __half* __restrict__ w2,
           const float* __restrict__ bq, const float* __restrict__ bk,
           const float* __restrict__ bv, __half* __restrict__ oq,
           __half* __restrict__ ok, __half* __restrict__ ov, float qscale) {
    const int z = blockIdx.z;
    const __half* A  = (z == 0) ? aq : (z == 1) ? ak : av;
    const __half* Wt = (z == 0) ? w0 : (z == 1) ? w1 : w2;
    const float* bias = (z == 0) ? bq : (z == 1) ? bk : bv;
    __half* Ch = (z == 0) ? oq : (z == 1) ? ok : ov;
    gemm_body(A, Wt, bias, (z == 0) ? qscale : 1.f, nullptr, Ch);
}

__global__ __launch_bounds__(256, 2)
void gemm1(const __half* __restrict__ A, const __half* __restrict__ Wt,
           const float* __restrict__ bias, float* __restrict__ Cf) {
    gemm_body(A, Wt, bias, 1.f, Cf, nullptr);
}

// ---------------- fp16 flash attention (causal, double-buffered K/V) ----------------
// CTA = 128 queries of one (b,h); 8 warps, warp = 16 queries x 64 keys.
// Q pre-scaled by 0.125*log2(e) (folded into Wq/bq). One __syncthreads per tile.
#define AQ 36   // u32 stride (72 halves); conflict-free fragment LDS
#define ATTN_SMEM_BYTES ((128 * AQ + 2 * 64 * AQ + 2 * 64 * AQ) * 4)   // 55296

__global__ __launch_bounds__(256, 2)
void attn_h(const __half* __restrict__ qh, const __half* __restrict__ kh,
            const __half* __restrict__ vh, __half* __restrict__ out) {
    extern __shared__ uint32_t smA[];
    uint32_t* Qs = smA;                    // [128][AQ]
    uint32_t* Ks = Qs + 128 * AQ;          // 2 x [64][AQ]
    uint32_t* Vt = Ks + 2 * 64 * AQ;       // 2 x [64 d][AQ]  (half2: even,odd key)

    const int tid = threadIdx.x;
    const int w = tid >> 5, lane = tid & 31, g = lane >> 2, t = lane & 3;
    const int qb = blockIdx.x, h = blockIdx.y, bb = blockIdx.z;
    const int q0 = qb * 128, wq = w * 16;

    const __half* Qb = qh + (size_t)bb * SEQ * DM + h * HD;
    const __half* Kb = kh + (size_t)bb * SEQ * DM + h * HD;
    const __half* Vb = vh + (size_t)bb * SEQ * DM + h * HD;

    #pragma unroll
    for (int r = 0; r < 4; r++) {
        int idx = tid + r * 256, row = idx >> 3, c = idx & 7;
        uint4 v = *(const uint4*)&Qb[(size_t)(q0 + row) * DM + c * 8];
        *(uint4*)&Qs[row * AQ + c * 4] = v;
    }

    float ofr[8][4] = {};
    float m0 = -1e30f, m1 = -1e30f, l0 = 0.f, l1 = 0.f;
    const int ntiles = 2 * qb + 2;
    const int kp = tid & 31, dg = tid >> 5;

    // prefetch + store tile 0 into stage 0
    uint4 pk[2], pva, pvb;
    #pragma unroll
    for (int r = 0; r < 2; r++) {
        int idx = tid + r * 256, row = idx >> 3, c = idx & 7;
        pk[r] = *(const uint4*)&Kb[(size_t)row * DM + c * 8];
    }
    pva = *(const uint4*)&Vb[(size_t)(2 * kp) * DM + dg * 8];
    pvb = *(const uint4*)&Vb[(size_t)(2 * kp + 1) * DM + dg * 8];
    {
        #pragma unroll
        for (int r = 0; r < 2; r++) {
            int idx = tid + r * 256, row = idx >> 3, c = idx & 7;
            *(uint4*)&Ks[row * AQ + c * 4] = pk[r];
        }
        __half ha[8], hb[8];
        *(uint4*)ha = pva; *(uint4*)hb = pvb;
        #pragma unroll
        for (int j = 0; j < 8; j++) {
            __half2 p = __halves2half2(ha[j], hb[j]);
            Vt[(dg * 8 + j) * AQ + kp] = *(uint32_t*)&p;
        }
    }
    __syncthreads();

    for (int jt = 0; jt < ntiles; jt++) {
        const int j0 = jt * 64;
        const int s = jt & 1;
        uint32_t* KsS = Ks + s * 64 * AQ;
        uint32_t* VtS = Vt + s * 64 * AQ;

        // issue next tile's global loads (latency hidden behind compute)
        const bool more = (jt + 1 < ntiles);
        if (more) {
            int jn = j0 + 64;
            #pragma unroll
            for (int r = 0; r < 2; r++) {
                int idx = tid + r * 256, row = idx >> 3, c = idx & 7;
                pk[r] = *(const uint4*)&Kb[(size_t)(jn + row) * DM + c * 8];
            }
            pva = *(const uint4*)&Vb[(size_t)(jn + 2 * kp) * DM + dg * 8];
            pvb = *(const uint4*)&Vb[(size_t)(jn + 2 * kp + 1) * DM + dg * 8];
        }

        // S = Q K^T
        float sc[8][4] = {};
        #pragma unroll
        for (int kk = 0; kk < 4; kk++) {
            uint32_t a0 = Qs[(wq + g) * AQ + kk * 8 + t];
            uint32_t a1 = Qs[(wq + g + 8) * AQ + kk * 8 + t];
            uint32_t a2 = Qs[(wq + g) * AQ + kk * 8 + t + 4];
            uint32_t a3 = Qs[(wq + g + 8) * AQ + kk * 8 + t + 4];
            #pragma unroll
            for (int nt = 0; nt < 8; nt++) {
                uint32_t b0 = KsS[(nt * 8 + g) * AQ + kk * 8 + t];
                uint32_t b1 = KsS[(nt * 8 + g) * AQ + kk * 8 + t + 4];
                mma_f16(sc[nt], a0, a1, a2, a3, b0, b1);
            }
        }

        // causal mask
        if (j0 + 63 > q0 + wq) {
            int r0 = q0 + wq + g, r1 = r0 + 8;
            #pragma unroll
            for (int nt = 0; nt < 8; nt++) {
                int key = j0 + nt * 8 + 2 * t;
                if (key > r0)     sc[nt][0] = -1e30f;
                if (key + 1 > r0) sc[nt][1] = -1e30f;
                if (key > r1)     sc[nt][2] = -1e30f;
                if (key + 1 > r1) sc[nt][3] = -1e30f;
            }
        }

        // online softmax (base-2; scale folded into Wq/bq)
        float tm0 = -1e30f, tm1 = -1e30f;
        #pragma unroll
        for (int nt = 0; nt < 8; nt++) {
            tm0 = fmaxf(tm0, fmaxf(sc[nt][0], sc[nt][1]));
            tm1 = fmaxf(tm1, fmaxf(sc[nt][2], sc[nt][3]));
        }
        tm0 = fmaxf(tm0, __shfl_xor_sync(0xffffffffu, tm0, 1));
        tm0 = fmaxf(tm0, __shfl_xor_sync(0xffffffffu, tm0, 2));
        tm1 = fmaxf(tm1, __shfl_xor_sync(0xffffffffu, tm1, 1));
        tm1 = fmaxf(tm1, __shfl_xor_sync(0xffffffffu, tm1, 2));

        float nm0 = fmaxf(m0, tm0), nm1 = fmaxf(m1, tm1);
        float al0 = exp2f(m0 - nm0), al1 = exp2f(m1 - nm1);
        m0 = nm0; m1 = nm1;

        float rs0 = 0.f, rs1 = 0.f;
        #pragma unroll
        for (int nt = 0; nt < 8; nt++) {
            sc[nt][0] = exp2f(sc[nt][0] - nm0); rs0 += sc[nt][0];
            sc[nt][1] = exp2f(sc[nt][1] - nm0); rs0 += sc[nt][1];
            sc[nt][2] = exp2f(sc[nt][2] - nm1); rs1 += sc[nt][2];
            sc[nt][3] = exp2f(sc[nt][3] - nm1); rs1 += sc[nt][3];
        }
        rs0 += __shfl_xor_sync(0xffffffffu, rs0, 1);
        rs0 += __shfl_xor_sync(0xffffffffu, rs0, 2);
        rs1 += __shfl_xor_sync(0xffffffffu, rs1, 1);
        rs1 += __shfl_xor_sync(0xffffffffu, rs1, 2);
        l0 = l0 * al0 + rs0;
        l1 = l1 * al1 + rs1;

        #pragma unroll
        for (int nt = 0; nt < 8; nt++) {
            ofr[nt][0] *= al0; ofr[nt][1] *= al0;
            ofr[nt][2] *= al1; ofr[nt][3] *= al1;
        }

        // P C-frag -> half2 A-frag, directly into PV mma (no smem round trip)
        #pragma unroll
        for (int c = 0; c < 4; c++) {
            __half2 h0 = __floats2half2_rn(sc[2 * c][0], sc[2 * c][1]);
            __half2 h1 = __floats2half2_rn(sc[2 * c][2], sc[2 * c][3]);
            __half2 h2 = __floats2half2_rn(sc[2 * c + 1][0], sc[2 * c + 1][1]);
            __half2 h3 = __floats2half2_rn(sc[2 * c + 1][2], sc[2 * c + 1][3]);
            uint32_t pa0 = *(uint32_t*)&h0, pa1 = *(uint32_t*)&h1;
            uint32_t pa2 = *(uint32_t*)&h2, pa3 = *(uint32_t*)&h3;
            #pragma unroll
            for (int dt = 0; dt < 8; dt++) {
                uint32_t b0 = VtS[(dt * 8 + g) * AQ + c * 8 + t];
                uint32_t b1 = VtS[(dt * 8 + g) * AQ + c * 8 + t + 4];
                mma_f16(ofr[dt], pa0, pa1, pa2, pa3, b0, b1);
            }
        }

        // store next tile to the other stage, then single barrier
        if (more) {
            uint32_t* KsN = Ks + (s ^ 1) * 64 * AQ;
            uint32_t* VtN = Vt + (s ^ 1) * 64 * AQ;
            #pragma unroll
            for (int r = 0; r < 2; r++) {
                int idx = tid + r * 256, row = idx >> 3, c = idx & 7;
                *(uint4*)&KsN[row * AQ + c * 4] = pk[r];
            }
            __half ha[8], hb[8];
            *(uint4*)ha = pva; *(uint4*)hb = pvb;
            #pragma unroll
            for (int j = 0; j < 8; j++) {
                __half2 p = __halves2half2(ha[j], hb[j]);
                VtN[(dg * 8 + j) * AQ + kp] = *(uint32_t*)&p;
            }
            __syncthreads();
        }
    }

    const float inv0 = 1.f / l0, inv1 = 1.f / l1;
    const int row0 = q0 + wq + g;
    #pragma unroll
    for (int dt = 0; dt < 8; dt++) {
        int col = h * HD + dt * 8 + 2 * t;
        __half2 v0 = __floats2half2_rn(ofr[dt][0] * inv0, ofr[dt][1] * inv0);
        *(uint32_t*)&out[((size_t)bb * SEQ + row0) * DM + col] = *(uint32_t*)&v0;
        __half2 v1 = __floats2half2_rn(ofr[dt][2] * inv1, ofr[dt][3] * inv1);
        *(uint32_t*)&out[((size_t)bb * SEQ + row0 + 8) * DM + col] = *(uint32_t*)&v1;
    }
}

// ----------------------------------------------------------------------------
extern "C" void kernel_launch(void* const* d_in, const int* in_sizes, int n_in,
                              void* d_out, int out_size) {
    const float* q  = (const float*)d_in[0];
    const float* k  = (const float*)d_in[1];
    const float* v  = (const float*)d_in[2];
    const float* Wq = (const float*)d_in[3];
    const float* bq = (const float*)d_in[4];
    const float* Wk = (const float*)d_in[5];
    const float* bk = (const float*)d_in[6];
    const float* Wv = (const float*)d_in[7];
    const float* bv = (const float*)d_in[8];
    const float* Wo = (const float*)d_in[9];
    const float* bo = (const float*)d_in[10];
    float* out = (float*)d_out;

    __half *aq, *ak, *av, *w0, *w1, *w2, *wo, *qh, *kh, *vh, *ao;
    cudaGetSymbolAddress((void**)&aq, g_aq);
    cudaGetSymbolAddress((void**)&ak, g_ak);
    cudaGetSymbolAddress((void**)&av, g_av);
    cudaGetSymbolAddress((void**)&w0, g_wt0);
    cudaGetSymbolAddress((void**)&w1, g_wt1);
    cudaGetSymbolAddress((void**)&w2, g_wt2);
    cudaGetSymbolAddress((void**)&wo, g_wto);
    cudaGetSymbolAddress((void**)&qh, g_qh);
    cudaGetSymbolAddress((void**)&kh, g_kh);
    cudaGetSymbolAddress((void**)&vh, g_vh);
    cudaGetSymbolAddress((void**)&ao, g_ao);

    const float QSCALE = 0.125f * 1.44269504088896f;  // 1/sqrt(64) * log2(e)
    const int n8 = MTOT * DM / 8;

    cudaFuncSetAttribute(attn_h, cudaFuncAttributeMaxDynamicSharedMemorySize,
                         ATTN_SMEM_BYTES);

    conv3<<<dim3(n8 / 256, 3), 256>>>(q, k, v, aq, ak, av, n8);
    trans3<<<dim3(DM / 32, DM / 32, 3), dim3(32, 8)>>>(Wq, Wk, Wv, w0, w1, w2, QSCALE);
    gemm3<<<dim3(DM / 128, MTOT / 128, 3), 256>>>(aq, ak, av, w0, w1, w2,
                                                  bq, bk, bv, qh, kh, vh, QSCALE);
    // Wo transpose is independent of attention: run it before the join.
    trans1<<<dim3(DM / 32, DM / 32), dim3(32, 8)>>>(Wo, wo);

    attn_h<<<dim3(SEQ / 128, NH, BATCH), 256, ATTN_SMEM_BYTES>>>(qh, kh, vh, ao);

    gemm1<<<dim3(DM / 128, MTOT / 128), 256>>>(ao, wo, bo, out);
}

// round 11
// speedup vs baseline: 5.6510x; 1.0361x over previous
#include <cuda_runtime.h>
#include <cuda_fp16.h>
#include <math.h>
#include <stdint.h>

#define BATCH 2
#define SEQ   2048
#define DM    1024
#define NH    16
#define HD    64
#define MTOT  (BATCH*SEQ)   // 4096

// ---------------- scratch (allocation-free) ----------------
__device__ __half g_aq[MTOT * DM];
__device__ __half g_ak[MTOT * DM];
__device__ __half g_av[MTOT * DM];
__device__ __half g_wt0[DM * DM];
__device__ __half g_wt1[DM * DM];
__device__ __half g_wt2[DM * DM];
__device__ __half g_wto[DM * DM];
__device__ __half g_qh[MTOT * DM];
__device__ __half g_kh[MTOT * DM];
__device__ __half g_vh[MTOT * DM];
__device__ __half g_ao[MTOT * DM];

// fp16 mma m16n8k16, fp32 accum
__device__ __forceinline__ void mma_f16(float d[4],
    uint32_t a0, uint32_t a1, uint32_t a2, uint32_t a3,
    uint32_t b0, uint32_t b1) {
    asm volatile(
        "mma.sync.aligned.m16n8k16.row.col.f32.f16.f16.f32 "
        "{%0,%1,%2,%3}, {%4,%5,%6,%7}, {%8,%9}, {%0,%1,%2,%3};\n"
        : "+f"(d[0]), "+f"(d[1]), "+f"(d[2]), "+f"(d[3])
        : "r"(a0), "r"(a1), "r"(a2), "r"(a3), "r"(b0), "r"(b1));
}

__device__ __forceinline__ void ldm_x4(uint32_t& r0, uint32_t& r1,
                                       uint32_t& r2, uint32_t& r3, uint32_t addr) {
    asm volatile("ldmatrix.sync.aligned.m8n8.x4.shared.b16 {%0,%1,%2,%3}, [%4];"
        : "=r"(r0), "=r"(r1), "=r"(r2), "=r"(r3) : "r"(addr));
}
__device__ __forceinline__ uint32_t sm_u32(const void* p) {
    return (uint32_t)__cvta_generic_to_shared(p);
}

// ---------------- prep kernels ----------------
__global__ __launch_bounds__(256)
void conv3(const float* __restrict__ q, const float* __restrict__ k,
           const float* __restrict__ v, __half* __restrict__ oq,
           __half* __restrict__ ok, __half* __restrict__ ov, int n8) {
    int i = blockIdx.x * 256 + threadIdx.x;
    if (i >= n8) return;
    const float* in = (blockIdx.y == 0) ? q : (blockIdx.y == 1) ? k : v;
    __half* out = (blockIdx.y == 0) ? oq : (blockIdx.y == 1) ? ok : ov;
    float4 v0 = ((const float4*)in)[2 * i];
    float4 v1 = ((const float4*)in)[2 * i + 1];
    __half2 p0 = __floats2half2_rn(v0.x, v0.y);
    __half2 p1 = __floats2half2_rn(v0.z, v0.w);
    __half2 p2 = __floats2half2_rn(v1.x, v1.y);
    __half2 p3 = __floats2half2_rn(v1.z, v1.w);
    uint4 o;
    o.x = *(uint32_t*)&p0; o.y = *(uint32_t*)&p1;
    o.z = *(uint32_t*)&p2; o.w = *(uint32_t*)&p3;
    ((uint4*)out)[i] = o;
}

// W[K][N] fp32 -> Wt[N][K] fp16 (scaled)
__device__ __forceinline__ void transpose_body(const float* __restrict__ W,
                                               __half* __restrict__ Wt, float scale) {
    __shared__ float tile[32][33];
    const int k0 = blockIdx.x * 32, n0 = blockIdx.y * 32;
    const int tx = threadIdx.x, ty = threadIdx.y;   // 32 x 8
    #pragma unroll
    for (int r = 0; r < 4; r++)
        tile[ty + 8 * r][tx] = W[(size_t)(k0 + ty + 8 * r) * DM + n0 + tx];
    __syncthreads();
    #pragma unroll
    for (int r = 0; r < 4; r++)
        Wt[(size_t)(n0 + ty + 8 * r) * DM + k0 + tx] =
            __float2half_rn(tile[tx][ty + 8 * r] * scale);
}

__global__ __launch_bounds__(256)
void trans3(const float* __restrict__ W0, const float* __restrict__ W1,
            const float* __restrict__ W2, __half* __restrict__ T0,
            __half* __restrict__ T1, __half* __restrict__ T2, float qs) {
    const int z = blockIdx.z;
    const float* W = (z == 0) ? W0 : (z == 1) ? W1 : W2;
    __half* T = (z == 0) ? T0 : (z == 1) ? T1 : T2;
    transpose_body(W, T, (z == 0) ? qs : 1.f);
}

__global__ __launch_bounds__(256)
void trans1(const float* __restrict__ W, __half* __restrict__ T) {
    transpose_body(W, T, 1.f);
}

// ---------------- fp16 GEMM body (ldmatrix) ----------------
#define GSTR 20   // u32 per row (40 halves); ldmatrix phases conflict-free

__device__ __forceinline__ void gemm_body(const __half* __restrict__ A,
        const __half* __restrict__ Wt, const float* __restrict__ bias, float bscale,
        float* __restrict__ Cf, __half* __restrict__ Ch) {
    __shared__ uint32_t As[128 * GSTR];
    __shared__ uint32_t Bs[128 * GSTR];
    const int tid = threadIdx.x;
    const int wid = tid >> 5, lane = tid & 31, g = lane >> 2, t = lane & 3;
    const int lrow = lane & 15, lhi = lane >> 4;
    const int n0 = blockIdx.x * 128, m0 = blockIdx.y * 128;
    const int wm = (wid >> 1) * 32, wn = (wid & 1) * 64;

    float acc[16][4] = {};
    uint4 pa[2], pb[2];

    const uint32_t aBase = sm_u32(As) + (uint32_t)(((wm + lrow) * GSTR + lhi * 4) * 4);
    const uint32_t bBase = sm_u32(Bs) + (uint32_t)(((wn + lrow) * GSTR + lhi * 4) * 4);

    #pragma unroll
    for (int it = 0; it < 2; it++) {
        int idx = tid + it * 256, row = idx >> 2, c = idx & 3;
        pa[it] = *(const uint4*)&A[(size_t)(m0 + row) * DM + c * 8];
        pb[it] = *(const uint4*)&Wt[(size_t)(n0 + row) * DM + c * 8];
    }

    for (int k0 = 0; k0 < DM; k0 += 32) {
        __syncthreads();
        #pragma unroll
        for (int it = 0; it < 2; it++) {
            int idx = tid + it * 256, row = idx >> 2, c = idx & 3;
            *(uint4*)&As[row * GSTR + c * 4] = pa[it];
            *(uint4*)&Bs[row * GSTR + c * 4] = pb[it];
        }
        __syncthreads();

        if (k0 + 32 < DM) {
            int kn = k0 + 32;
            #pragma unroll
            for (int it = 0; it < 2; it++) {
                int idx = tid + it * 256, row = idx >> 2, c = idx & 3;
                pa[it] = *(const uint4*)&A[(size_t)(m0 + row) * DM + kn + c * 8];
                pb[it] = *(const uint4*)&Wt[(size_t)(n0 + row) * DM + kn + c * 8];
            }
        }

        #pragma unroll
        for (int kk = 0; kk < 2; kk++) {
            uint32_t af[2][4], bf[8][2];
            #pragma unroll
            for (int mt = 0; mt < 2; mt++)
                ldm_x4(af[mt][0], af[mt][1], af[mt][2], af[mt][3],
                       aBase + (uint32_t)(mt * 16 * GSTR * 4 + kk * 32));
            #pragma unroll
            for (int np = 0; np < 4; np++) {
                uint32_t r0, r1, r2, r3;
                ldm_x4(r0, r1, r2, r3, bBase + (uint32_t)(np * 16 * GSTR * 4 + kk * 32));
                bf[2 * np][0] = r0; bf[2 * np + 1][0] = r1;
                bf[2 * np][1] = r2; bf[2 * np + 1][1] = r3;
            }
            #pragma unroll
            for (int mt = 0; mt < 2; mt++)
                #pragma unroll
                for (int nt = 0; nt < 8; nt++)
                    mma_f16(acc[mt * 8 + nt], af[mt][0], af[mt][1], af[mt][2], af[mt][3],
                            bf[nt][0], bf[nt][1]);
        }
    }

    #pragma unroll
    for (int mt = 0; mt < 2; mt++) {
        int row = m0 + wm + mt * 16 + g;
        #pragma unroll
        for (int nt = 0; nt < 8; nt++) {
            int col = n0 + wn + nt * 8 + 2 * t;
            float b0 = bias[col] * bscale, b1 = bias[col + 1] * bscale;
            float* a = acc[mt * 8 + nt];
            float v00 = a[0] + b0, v01 = a[1] + b1;
            float v10 = a[2] + b0, v11 = a[3] + b1;
            if (Cf) {
                float2 x0 = { v00, v01 };
                *(float2*)&Cf[(size_t)row * DM + col] = x0;
                float2 x1 = { v10, v11 };
                *(float2*)&Cf[(size_t)(row + 8) * DM + col] = x1;
            }
            if (Ch) {
                __half2 h0 = __floats2half2_rn(v00, v01);
                *(uint32_t*)&Ch[(size_t)row * DM + col] = *(uint32_t*)&h0;
                __half2 h1 = __floats2half2_rn(v10, v11);
                *(uint32_t*)&Ch[(size_t)(row + 8) * DM + col] = *(uint32_t*)&h1;
            }
        }
    }
}

__global__ __launch_bounds__(256, 2)
void gemm3(const __half* __restrict__ aq, const __half* __restrict__ ak,
           const __half* __restrict__ av, const __half* __restrict__ w0,
           const __half* __restrict__ w1, const __half* __restrict__ w2,
           const float* __restrict__ bq, const float* __restrict__ bk,
           const float* __restrict__ bv, __half* __restrict__ oq,
           __half* __restrict__ ok, __half* __restrict__ ov, float qscale) {
    const int z = blockIdx.z;
    const __half* A  = (z == 0) ? aq : (z == 1) ? ak : av;
    const __half* Wt = (z == 0) ? w0 : (z == 1) ? w1 : w2;
    const float* bias = (z == 0) ? bq : (z == 1) ? bk : bv;
    __half* Ch = (z == 0) ? oq : (z == 1) ? ok : ov;
    gemm_body(A, Wt, bias, (z == 0) ? qscale : 1.f, nullptr, Ch);
}

__global__ __launch_bounds__(256, 2)
void gemm1(const __half* __restrict__ A, const __half* __restrict__ Wt,
           const float* __restrict__ bias, float* __restrict__ Cf) {
    gemm_body(A, Wt, bias, 1.f, Cf, nullptr);
}

// ---------------- fp16 flash attention (causal, double-buffered, ldmatrix) ----
#define AQ 36   // u32 stride (72 halves)
#define ATTN_SMEM_BYTES ((128 * AQ + 2 * 64 * AQ + 2 * 64 * AQ) * 4)   // 55296

__global__ __launch_bounds__(256, 2)
void attn_h(const __half* __restrict__ qh, const __half* __restrict__ kh,
            const __half* __restrict__ vh, __half* __restrict__ out) {
    extern __shared__ uint32_t smA[];
    uint32_t* Qs = smA;                    // [128][AQ]
    uint32_t* Ks = Qs + 128 * AQ;          // 2 x [64][AQ]  key-major
    uint32_t* Vt = Ks + 2 * 64 * AQ;       // 2 x [64 d][AQ] (half2: even,odd key)

    const int tid = threadIdx.x;
    const int w = tid >> 5, lane = tid & 31, g = lane >> 2, t = lane & 3;
    const int lrow = lane & 15, lhi = lane >> 4;
    const int qb = blockIdx.x, h = blockIdx.y, bb = blockIdx.z;
    const int q0 = qb * 128, wq = w * 16;

    const __half* Qb = qh + (size_t)bb * SEQ * DM + h * HD;
    const __half* Kb = kh + (size_t)bb * SEQ * DM + h * HD;
    const __half* Vb = vh + (size_t)bb * SEQ * DM + h * HD;

    #pragma unroll
    for (int r = 0; r < 4; r++) {
        int idx = tid + r * 256, row = idx >> 3, c = idx & 7;
        uint4 v = *(const uint4*)&Qb[(size_t)(q0 + row) * DM + c * 8];
        *(uint4*)&Qs[row * AQ + c * 4] = v;
    }

    const uint32_t qBase = sm_u32(Qs) + (uint32_t)(((wq + lrow) * AQ + lhi * 4) * 4);
    const uint32_t kBase = sm_u32(Ks) + (uint32_t)((lrow * AQ + lhi * 4) * 4);
    const uint32_t vBase = sm_u32(Vt) + (uint32_t)((lrow * AQ + lhi * 4) * 4);
    const uint32_t stageB = (uint32_t)(64 * AQ * 4);

    float ofr[8][4] = {};
    float m0 = -1e30f, m1 = -1e30f, l0 = 0.f, l1 = 0.f;
    const int ntiles = 2 * qb + 2;
    const int kp = tid & 31, dg = tid >> 5;

    uint4 pk[2], pva, pvb;
    #pragma unroll
    for (int r = 0; r < 2; r++) {
        int idx = tid + r * 256, row = idx >> 3, c = idx & 7;
        pk[r] = *(const uint4*)&Kb[(size_t)row * DM + c * 8];
    }
    pva = *(const uint4*)&Vb[(size_t)(2 * kp) * DM + dg * 8];
    pvb = *(const uint4*)&Vb[(size_t)(2 * kp + 1) * DM + dg * 8];
    {
        #pragma unroll
        for (int r = 0; r < 2; r++) {
            int idx = tid + r * 256, row = idx >> 3, c = idx & 7;
            *(uint4*)&Ks[row * AQ + c * 4] = pk[r];
        }
        __half ha[8], hb[8];
        *(uint4*)ha = pva; *(uint4*)hb = pvb;
        #pragma unroll
        for (int j = 0; j < 8; j++) {
            __half2 p = __halves2half2(ha[j], hb[j]);
            Vt[(dg * 8 + j) * AQ + kp] = *(uint32_t*)&p;
        }
    }
    __syncthreads();

    for (int jt = 0; jt < ntiles; jt++) {
        const int j0 = jt * 64;
        const int s = jt & 1;
        const uint32_t kStage = kBase + s * stageB;
        const uint32_t vStage = vBase + s * stageB;

        const bool more = (jt + 1 < ntiles);
        if (more) {
            int jn = j0 + 64;
            #pragma unroll
            for (int r = 0; r < 2; r++) {
                int idx = tid + r * 256, row = idx >> 3, c = idx & 7;
                pk[r] = *(const uint4*)&Kb[(size_t)(jn + row) * DM + c * 8];
            }
            pva = *(const uint4*)&Vb[(size_t)(jn + 2 * kp) * DM + dg * 8];
            pvb = *(const uint4*)&Vb[(size_t)(jn + 2 * kp + 1) * DM + dg * 8];
        }

        // S = Q K^T
        float sc[8][4] = {};
        #pragma unroll
        for (int kk = 0; kk < 4; kk++) {
            uint32_t a0, a1, a2, a3;
            ldm_x4(a0, a1, a2, a3, qBase + (uint32_t)(kk * 32));
            #pragma unroll
            for (int np = 0; np < 4; np++) {
                uint32_t r0, r1, r2, r3;
                ldm_x4(r0, r1, r2, r3,
                       kStage + (uint32_t)(np * 16 * AQ * 4 + kk * 32));
                mma_f16(sc[2 * np],     a0, a1, a2, a3, r0, r2);
                mma_f16(sc[2 * np + 1], a0, a1, a2, a3, r1, r3);
            }
        }

        // causal mask
        if (j0 + 63 > q0 + wq) {
            int r0 = q0 + wq + g, r1 = r0 + 8;
            #pragma unroll
            for (int nt = 0; nt < 8; nt++) {
                int key = j0 + nt * 8 + 2 * t;
                if (key > r0)     sc[nt][0] = -1e30f;
                if (key + 1 > r0) sc[nt][1] = -1e30f;
                if (key > r1)     sc[nt][2] = -1e30f;
                if (key + 1 > r1) sc[nt][3] = -1e30f;
            }
        }

        // online softmax (base-2; scale folded into Wq/bq)
        float tm0 = -1e30f, tm1 = -1e30f;
        #pragma unroll
        for (int nt = 0; nt < 8; nt++) {
            tm0 = fmaxf(tm0, fmaxf(sc[nt][0], sc[nt][1]));
            tm1 = fmaxf(tm1, fmaxf(sc[nt][2], sc[nt][3]));
        }
        tm0 = fmaxf(tm0, __shfl_xor_sync(0xffffffffu, tm0, 1));
        tm0 = fmaxf(tm0, __shfl_xor_sync(0xffffffffu, tm0, 2));
        tm1 = fmaxf(tm1, __shfl_xor_sync(0xffffffffu, tm1, 1));
        tm1 = fmaxf(tm1, __shfl_xor_sync(0xffffffffu, tm1, 2));

        float nm0 = fmaxf(m0, tm0), nm1 = fmaxf(m1, tm1);
        float al0 = exp2f(m0 - nm0), al1 = exp2f(m1 - nm1);
        m0 = nm0; m1 = nm1;

        float rs0 = 0.f, rs1 = 0.f;
        #pragma unroll
        for (int nt = 0; nt < 8; nt++) {
            sc[nt][0] = exp2f(sc[nt][0] - nm0); rs0 += sc[nt][0];
            sc[nt][1] = exp2f(sc[nt][1] - nm0); rs0 += sc[nt][1];
            sc[nt][2] = exp2f(sc[nt][2] - nm1); rs1 += sc[nt][2];
            sc[nt][3] = exp2f(sc[nt][3] - nm1); rs1 += sc[nt][3];
        }
        rs0 += __shfl_xor_sync(0xffffffffu, rs0, 1);
        rs0 += __shfl_xor_sync(0xffffffffu, rs0, 2);
        rs1 += __shfl_xor_sync(0xffffffffu, rs1, 1);
        rs1 += __shfl_xor_sync(0xffffffffu, rs1, 2);
        l0 = l0 * al0 + rs0;
        l1 = l1 * al1 + rs1;

        #pragma unroll
        for (int nt = 0; nt < 8; nt++) {
            ofr[nt][0] *= al0; ofr[nt][1] *= al0;
            ofr[nt][2] *= al1; ofr[nt][3] *= al1;
        }

        // P C-frag -> half2 A-frag, straight into PV mma
        #pragma unroll
        for (int c = 0; c < 4; c++) {
            __half2 h0 = __floats2half2_rn(sc[2 * c][0], sc[2 * c][1]);
            __half2 h1 = __floats2half2_rn(sc[2 * c][2], sc[2 * c][3]);
            __half2 h2 = __floats2half2_rn(sc[2 * c + 1][0], sc[2 * c + 1][1]);
            __half2 h3 = __floats2half2_rn(sc[2 * c + 1][2], sc[2 * c + 1][3]);
            uint32_t pa0 = *(uint32_t*)&h0, pa1 = *(uint32_t*)&h1;
            uint32_t pa2 = *(uint32_t*)&h2, pa3 = *(uint32_t*)&h3;
            #pragma unroll
            for (int dp = 0; dp < 4; dp++) {
                uint32_t r0, r1, r2, r3;
                ldm_x4(r0, r1, r2, r3,
                       vStage + (uint32_t)(dp * 16 * AQ * 4 + c * 32));
                mma_f16(ofr[2 * dp],     pa0, pa1, pa2, pa3, r0, r2);
                mma_f16(ofr[2 * dp + 1], pa0, pa1, pa2, pa3, r1, r3);
            }
        }

        if (more) {
            uint32_t* KsN = Ks + (s ^ 1) * 64 * AQ;
            uint32_t* VtN = Vt + (s ^ 1) * 64 * AQ;
            #pragma unroll
            for (int r = 0; r < 2; r++) {
                int idx = tid + r * 256, row = idx >> 3, c = idx & 7;
                *(uint4*)&KsN[row * AQ + c * 4] = pk[r];
            }
            __half ha[8], hb[8];
            *(uint4*)ha = pva; *(uint4*)hb = pvb;
            #pragma unroll
            for (int j = 0; j < 8; j++) {
                __half2 p = __halves2half2(ha[j], hb[j]);
                VtN[(dg * 8 + j) * AQ + kp] = *(uint32_t*)&p;
            }
            __syncthreads();
        }
    }

    const float inv0 = 1.f / l0, inv1 = 1.f / l1;
    const int row0 = q0 + wq + g;
    #pragma unroll
    for (int dt = 0; dt < 8; dt++) {
        int col = h * HD + dt * 8 + 2 * t;
        __half2 v0 = __floats2half2_rn(ofr[dt][0] * inv0, ofr[dt][1] * inv0);
        *(uint32_t*)&out[((size_t)bb * SEQ + row0) * DM + col] = *(uint32_t*)&v0;
        __half2 v1 = __floats2half2_rn(ofr[dt][2] * inv1, ofr[dt][3] * inv1);
        *(uint32_t*)&out[((size_t)bb * SEQ + row0 + 8) * DM + col] = *(uint32_t*)&v1;
    }
}

// ----------------------------------------------------------------------------
extern "C" void kernel_launch(void* const* d_in, const int* in_sizes, int n_in,
                              void* d_out, int out_size) {
    const float* q  = (const float*)d_in[0];
    const float* k  = (const float*)d_in[1];
    const float* v  = (const float*)d_in[2];
    const float* Wq = (const float*)d_in[3];
    const float* bq = (const float*)d_in[4];
    const float* Wk = (const float*)d_in[5];
    const float* bk = (const float*)d_in[6];
    const float* Wv = (const float*)d_in[7];
    const float* bv = (const float*)d_in[8];
    const float* Wo = (const float*)d_in[9];
    const float* bo = (const float*)d_in[10];
    float* out = (float*)d_out;

    __half *aq, *ak, *av, *w0, *w1, *w2, *wo, *qh, *kh, *vh, *ao;
    cudaGetSymbolAddress((void**)&aq, g_aq);
    cudaGetSymbolAddress((void**)&ak, g_ak);
    cudaGetSymbolAddress((void**)&av, g_av);
    cudaGetSymbolAddress((void**)&w0, g_wt0);
    cudaGetSymbolAddress((void**)&w1, g_wt1);
    cudaGetSymbolAddress((void**)&w2, g_wt2);
    cudaGetSymbolAddress((void**)&wo, g_wto);
    cudaGetSymbolAddress((void**)&qh, g_qh);
    cudaGetSymbolAddress((void**)&kh, g_kh);
    cudaGetSymbolAddress((void**)&vh, g_vh);
    cudaGetSymbolAddress((void**)&ao, g_ao);

    const float QSCALE = 0.125f * 1.44269504088896f;  // 1/sqrt(64) * log2(e)
    const int n8 = MTOT * DM / 8;

    cudaFuncSetAttribute(attn_h, cudaFuncAttributeMaxDynamicSharedMemorySize,
                         ATTN_SMEM_BYTES);

    conv3<<<dim3(n8 / 256, 3), 256>>>(q, k, v, aq, ak, av, n8);
    trans3<<<dim3(DM / 32, DM / 32, 3), dim3(32, 8)>>>(Wq, Wk, Wv, w0, w1, w2, QSCALE);
    gemm3<<<dim3(DM / 128, MTOT / 128, 3), 256>>>(aq, ak, av, w0, w1, w2,
                                                  bq, bk, bv, qh, kh, vh, QSCALE);
    trans1<<<dim3(DM / 32, DM / 32), dim3(32, 8)>>>(Wo, wo);

    attn_h<<<dim3(SEQ / 128, NH, BATCH), 256, ATTN_SMEM_BYTES>>>(qh, kh, vh, ao);

    gemm1<<<dim3(DM / 128, MTOT / 128), 256>>>(ao, wo, bo, out);
}

// round 15
// speedup vs baseline: 6.1320x; 1.0851x over previous
#include <cuda_runtime.h>
#include <cuda_fp16.h>
#include <math.h>
#include <stdint.h>

#define BATCH 2
#define SEQ   2048
#define DM    1024
#define NH    16
#define HD    64
#define MTOT  (BATCH*SEQ)   // 4096

// ---------------- scratch (allocation-free) ----------------
__device__ __half g_aq[MTOT * DM];
__device__ __half g_ak[MTOT * DM];
__device__ __half g_av[MTOT * DM];
__device__ __half g_wt0[DM * DM];
__device__ __half g_wt1[DM * DM];
__device__ __half g_wt2[DM * DM];
__device__ __half g_wto[DM * DM];
__device__ __half g_qh[MTOT * DM];
__device__ __half g_kh[MTOT * DM];
__device__ __half g_vh[MTOT * DM];
__device__ __half g_ao[MTOT * DM];

// fp16 mma m16n8k16, fp32 accum
__device__ __forceinline__ void mma_f16(float d[4],
    uint32_t a0, uint32_t a1, uint32_t a2, uint32_t a3,
    uint32_t b0, uint32_t b1) {
    asm volatile(
        "mma.sync.aligned.m16n8k16.row.col.f32.f16.f16.f32 "
        "{%0,%1,%2,%3}, {%4,%5,%6,%7}, {%8,%9}, {%0,%1,%2,%3};\n"
        : "+f"(d[0]), "+f"(d[1]), "+f"(d[2]), "+f"(d[3])
        : "r"(a0), "r"(a1), "r"(a2), "r"(a3), "r"(b0), "r"(b1));
}

__device__ __forceinline__ void ldm_x4(uint32_t& r0, uint32_t& r1,
                                       uint32_t& r2, uint32_t& r3, uint32_t addr) {
    asm volatile("ldmatrix.sync.aligned.m8n8.x4.shared.b16 {%0,%1,%2,%3}, [%4];"
        : "=r"(r0), "=r"(r1), "=r"(r2), "=r"(r3) : "r"(addr));
}
__device__ __forceinline__ uint32_t sm_u32(const void* p) {
    return (uint32_t)__cvta_generic_to_shared(p);
}
__device__ __forceinline__ void cpa16(uint32_t dst, const void* src) {
    asm volatile("cp.async.cg.shared.global [%0], [%1], 16;" :: "r"(dst), "l"(src));
}
#define CP_COMMIT() asm volatile("cp.async.commit_group;" ::: "memory")
#define CP_WAIT1()  asm volatile("cp.async.wait_group 1;" ::: "memory")

// ---------------- prep kernels ----------------
__global__ __launch_bounds__(256)
void conv3(const float* __restrict__ q, const float* __restrict__ k,
           const float* __restrict__ v, __half* __restrict__ oq,
           __half* __restrict__ ok, __half* __restrict__ ov, int n8) {
    int i = blockIdx.x * 256 + threadIdx.x;
    if (i >= n8) return;
    const float* in = (blockIdx.y == 0) ? q : (blockIdx.y == 1) ? k : v;
    __half* out = (blockIdx.y == 0) ? oq : (blockIdx.y == 1) ? ok : ov;
    float4 v0 = ((const float4*)in)[2 * i];
    float4 v1 = ((const float4*)in)[2 * i + 1];
    __half2 p0 = __floats2half2_rn(v0.x, v0.y);
    __half2 p1 = __floats2half2_rn(v0.z, v0.w);
    __half2 p2 = __floats2half2_rn(v1.x, v1.y);
    __half2 p3 = __floats2half2_rn(v1.z, v1.w);
    uint4 o;
    o.x = *(uint32_t*)&p0; o.y = *(uint32_t*)&p1;
    o.z = *(uint32_t*)&p2; o.w = *(uint32_t*)&p3;
    ((uint4*)out)[i] = o;
}

// W[K][N] fp32 -> Wt[N][K] fp16 (scaled)
__device__ __forceinline__ void transpose_body(const float* __restrict__ W,
                                               __half* __restrict__ Wt, float scale) {
    __shared__ float tile[32][33];
    const int k0 = blockIdx.x * 32, n0 = blockIdx.y * 32;
    const int tx = threadIdx.x, ty = threadIdx.y;   // 32 x 8
    #pragma unroll
    for (int r = 0; r < 4; r++)
        tile[ty + 8 * r][tx] = W[(size_t)(k0 + ty + 8 * r) * DM + n0 + tx];
    __syncthreads();
    #pragma unroll
    for (int r = 0; r < 4; r++)
        Wt[(size_t)(n0 + ty + 8 * r) * DM + k0 + tx] =
            __float2half_rn(tile[tx][ty + 8 * r] * scale);
}

__global__ __launch_bounds__(256)
void trans3(const float* __restrict__ W0, const float* __restrict__ W1,
            const float* __restrict__ W2, __half* __restrict__ T0,
            __half* __restrict__ T1, __half* __restrict__ T2, float qs) {
    const int z = blockIdx.z;
    const float* W = (z == 0) ? W0 : (z == 1) ? W1 : W2;
    __half* T = (z == 0) ? T0 : (z == 1) ? T1 : T2;
    transpose_body(W, T, (z == 0) ? qs : 1.f);
}

__global__ __launch_bounds__(256)
void trans1(const float* __restrict__ W, __half* __restrict__ T) {
    transpose_body(W, T, 1.f);
}

// ---------------- fp16 GEMM (cp.async 3-stage, BK=64, 16 chunks) ----------------
// CTA 128x128, 8 warps (4x2), warp 32x64. Row stride 36 u32 = 144 B.
#define PSTR 36
#define NCHUNK 16                           // DM / 64
#define TILE_U32 (128 * PSTR)               // one 128x64 fp16 tile
#define STAGE_BYTES (2 * TILE_U32 * 4)      // A+B = 36864
#define GEMM_SMEM (3 * STAGE_BYTES)         // 110592

__device__ __forceinline__ void gemm_body(const __half* __restrict__ A,
        const __half* __restrict__ Wt, const float* __restrict__ bias, float bscale,
        float* __restrict__ Cf, __half* __restrict__ Ch) {
    extern __shared__ uint32_t gsm[];
    const int tid = threadIdx.x;
    const int wid = tid >> 5, lane = tid & 31, g = lane >> 2, t = lane & 3;
    const int lrow = lane & 15, lhi = lane >> 4;
    const int n0 = blockIdx.x * 128, m0 = blockIdx.y * 128;
    const int wm = (wid >> 1) * 32, wn = (wid & 1) * 64;

    const uint32_t smBase = sm_u32(gsm);

    auto issue = [&](int c, int s) {
        const uint32_t aB = smBase + s * STAGE_BYTES;
        const uint32_t bB = aB + TILE_U32 * 4;
        #pragma unroll
        for (int it = 0; it < 4; it++) {
            int idx = tid + it * 256;            // 0..1023
            int row = idx >> 3, col = idx & 7;
            uint32_t off = (uint32_t)((row * PSTR + col * 4) * 4);
            cpa16(aB + off, &A[(size_t)(m0 + row) * DM + c * 64 + col * 8]);
            cpa16(bB + off, &Wt[(size_t)(n0 + row) * DM + c * 64 + col * 8]);
        }
        CP_COMMIT();
    };

    issue(0, 0);
    issue(1, 1);

    float acc[16][4] = {};
    const uint32_t aOff = (uint32_t)(((wm + lrow) * PSTR + lhi * 4) * 4);
    const uint32_t bOff = (uint32_t)(TILE_U32 * 4 + ((wn + lrow) * PSTR + lhi * 4) * 4);

    #pragma unroll 1
    for (int c = 0; c < NCHUNK; c++) {
        const int st = c - (c / 3) * 3;
        CP_WAIT1();
        __syncthreads();
        if (c + 2 < NCHUNK) {
            int cn = c + 2;
            issue(cn, cn - (cn / 3) * 3);
        }
        const uint32_t aB = smBase + st * STAGE_BYTES + aOff;
        const uint32_t bB = smBase + st * STAGE_BYTES + bOff;
        #pragma unroll
        for (int kk = 0; kk < 4; kk++) {
            uint32_t af[2][4], bf[8][2];
            #pragma unroll
            for (int mt = 0; mt < 2; mt++)
                ldm_x4(af[mt][0], af[mt][1], af[mt][2], af[mt][3],
                       aB + (uint32_t)(mt * 16 * PSTR * 4 + kk * 32));
            #pragma unroll
            for (int np = 0; np < 4; np++) {
                uint32_t r0, r1, r2, r3;
                ldm_x4(r0, r1, r2, r3, bB + (uint32_t)(np * 16 * PSTR * 4 + kk * 32));
                bf[2 * np][0] = r0; bf[2 * np + 1][0] = r1;
                bf[2 * np][1] = r2; bf[2 * np + 1][1] = r3;
            }
            #pragma unroll
            for (int mt = 0; mt < 2; mt++)
                #pragma unroll
                for (int nt = 0; nt < 8; nt++)
                    mma_f16(acc[mt * 8 + nt], af[mt][0], af[mt][1], af[mt][2], af[mt][3],
                            bf[nt][0], bf[nt][1]);
        }
    }

    #pragma unroll
    for (int mt = 0; mt < 2; mt++) {
        int row = m0 + wm + mt * 16 + g;
        #pragma unroll
        for (int nt = 0; nt < 8; nt++) {
            int col = n0 + wn + nt * 8 + 2 * t;
            float b0 = bias[col] * bscale, b1 = bias[col + 1] * bscale;
            float* a = acc[mt * 8 + nt];
            float v00 = a[0] + b0, v01 = a[1] + b1;
            float v10 = a[2] + b0, v11 = a[3] + b1;
            if (Cf) {
                float2 x0 = { v00, v01 };
                *(float2*)&Cf[(size_t)row * DM + col] = x0;
                float2 x1 = { v10, v11 };
                *(float2*)&Cf[(size_t)(row + 8) * DM + col] = x1;
            }
            if (Ch) {
                __half2 h0 = __floats2half2_rn(v00, v01);
                *(uint32_t*)&Ch[(size_t)row * DM + col] = *(uint32_t*)&h0;
                __half2 h1 = __floats2half2_rn(v10, v11);
                *(uint32_t*)&Ch[(size_t)(row + 8) * DM + col] = *(uint32_t*)&h1;
            }
        }
    }
}

__global__ __launch_bounds__(256, 2)
void gemm3(const __half* __restrict__ aq, const __half* __restrict__ ak,
           const __half* __restrict__ av, const __half* __restrict__ w0,
           const __half* __restrict__ w1, const __half* __restrict__ w2,
           const float* __restrict__ bq, const float* __restrict__ bk,
           const float* __restrict__ bv, __half* __restrict__ oq,
           __half* __restrict__ ok, __half* __restrict__ ov, float qscale) {
    const int z = blockIdx.z;
    const __half* A  = (z == 0) ? aq : (z == 1) ? ak : av;
    const __half* Wt = (z == 0) ? w0 : (z == 1) ? w1 : w2;
    const float* bias = (z == 0) ? bq : (z == 1) ? bk : bv;
    __half* Ch = (z == 0) ? oq : (z == 1) ? ok : ov;
    gemm_body(A, Wt, bias, (z == 0) ? qscale : 1.f, nullptr, Ch);
}

__global__ __launch_bounds__(256, 2)
void gemm1(const __half* __restrict__ A, const __half* __restrict__ Wt,
           const float* __restrict__ bias, float* __restrict__ Cf) {
    gemm_body(A, Wt, bias, 1.f, Cf, nullptr);
}

// ---------------- fp16 flash attention (causal, double-buffered, ldmatrix) ----
#define AQ 36   // u32 stride (72 halves)
#define ATTN_SMEM_BYTES ((128 * AQ + 2 * 64 * AQ + 2 * 64 * AQ) * 4)   // 55296

__global__ __launch_bounds__(256, 2)
void attn_h(const __half* __restrict__ qh, const __half* __restrict__ kh,
            const __half* __restrict__ vh, __half* __restrict__ out) {
    extern __shared__ uint32_t smA[];
    uint32_t* Qs = smA;                    // [128][AQ]
    uint32_t* Ks = Qs + 128 * AQ;          // 2 x [64][AQ]  key-major
    uint32_t* Vt = Ks + 2 * 64 * AQ;       // 2 x [64 d][AQ] (half2: even,odd key)

    const int tid = threadIdx.x;
    const int w = tid >> 5, lane = tid & 31, g = lane >> 2, t = lane & 3;
    const int lrow = lane & 15, lhi = lane >> 4;
    const int qb = blockIdx.x, h = blockIdx.y, bb = blockIdx.z;
    const int q0 = qb * 128, wq = w * 16;

    const __half* Qb = qh + (size_t)bb * SEQ * DM + h * HD;
    const __half* Kb = kh + (size_t)bb * SEQ * DM + h * HD;
    const __half* Vb = vh + (size_t)bb * SEQ * DM + h * HD;

    #pragma unroll
    for (int r = 0; r < 4; r++) {
        int idx = tid + r * 256, row = idx >> 3, c = idx & 7;
        uint4 v = *(const uint4*)&Qb[(size_t)(q0 + row) * DM + c * 8];
        *(uint4*)&Qs[row * AQ + c * 4] = v;
    }

    const uint32_t qBase = sm_u32(Qs) + (uint32_t)(((wq + lrow) * AQ + lhi * 4) * 4);
    const uint32_t kBase = sm_u32(Ks) + (uint32_t)((lrow * AQ + lhi * 4) * 4);
    const uint32_t vBase = sm_u32(Vt) + (uint32_t)((lrow * AQ + lhi * 4) * 4);
    const uint32_t stageB = (uint32_t)(64 * AQ * 4);

    float ofr[8][4] = {};
    float m0 = -1e30f, m1 = -1e30f, l0 = 0.f, l1 = 0.f;
    const int ntiles = 2 * qb + 2;
    const int kp = tid & 31, dg = tid >> 5;

    uint4 pk[2], pva, pvb;
    #pragma unroll
    for (int r = 0; r < 2; r++) {
        int idx = tid + r * 256, row = idx >> 3, c = idx & 7;
        pk[r] = *(const uint4*)&Kb[(size_t)row * DM + c * 8];
    }
    pva = *(const uint4*)&Vb[(size_t)(2 * kp) * DM + dg * 8];
    pvb = *(const uint4*)&Vb[(size_t)(2 * kp + 1) * DM + dg * 8];
    {
        #pragma unroll
        for (int r = 0; r < 2; r++) {
            int idx = tid + r * 256, row = idx >> 3, c = idx & 7;
            *(uint4*)&Ks[row * AQ + c * 4] = pk[r];
        }
        __half ha[8], hb[8];
        *(uint4*)ha = pva; *(uint4*)hb = pvb;
        #pragma unroll
        for (int j = 0; j < 8; j++) {
            __half2 p = __halves2half2(ha[j], hb[j]);
            Vt[(dg * 8 + j) * AQ + kp] = *(uint32_t*)&p;
        }
    }
    __syncthreads();

    for (int jt = 0; jt < ntiles; jt++) {
        const int j0 = jt * 64;
        const int s = jt & 1;
        const uint32_t kStage = kBase + s * stageB;
        const uint32_t vStage = vBase + s * stageB;

        const bool more = (jt + 1 < ntiles);
        if (more) {
            int jn = j0 + 64;
            #pragma unroll
            for (int r = 0; r < 2; r++) {
                int idx = tid + r * 256, row = idx >> 3, c = idx & 7;
                pk[r] = *(const uint4*)&Kb[(size_t)(jn + row) * DM + c * 8];
            }
            pva = *(const uint4*)&Vb[(size_t)(jn + 2 * kp) * DM + dg * 8];
            pvb = *(const uint4*)&Vb[(size_t)(jn + 2 * kp + 1) * DM + dg * 8];
        }

        // S = Q K^T
        float sc[8][4] = {};
        #pragma unroll
        for (int kk = 0; kk < 4; kk++) {
            uint32_t a0, a1, a2, a3;
            ldm_x4(a0, a1, a2, a3, qBase + (uint32_t)(kk * 32));
            #pragma unroll
            for (int np = 0; np < 4; np++) {
                uint32_t r0, r1, r2, r3;
                ldm_x4(r0, r1, r2, r3,
                       kStage + (uint32_t)(np * 16 * AQ * 4 + kk * 32));
                mma_f16(sc[2 * np],     a0, a1, a2, a3, r0, r2);
                mma_f16(sc[2 * np + 1], a0, a1, a2, a3, r1, r3);
            }
        }

        // causal mask
        if (j0 + 63 > q0 + wq) {
            int r0 = q0 + wq + g, r1 = r0 + 8;
            #pragma unroll
            for (int nt = 0; nt < 8; nt++) {
                int key = j0 + nt * 8 + 2 * t;
                if (key > r0)     sc[nt][0] = -1e30f;
                if (key + 1 > r0) sc[nt][1] = -1e30f;
                if (key > r1)     sc[nt][2] = -1e30f;
                if (key + 1 > r1) sc[nt][3] = -1e30f;
            }
        }

        // online softmax (base-2; scale folded into Wq/bq)
        float tm0 = -1e30f, tm1 = -1e30f;
        #pragma unroll
        for (int nt = 0; nt < 8; nt++) {
            tm0 = fmaxf(tm0, fmaxf(sc[nt][0], sc[nt][1]));
            tm1 = fmaxf(tm1, fmaxf(sc[nt][2], sc[nt][3]));
        }
        tm0 = fmaxf(tm0, __shfl_xor_sync(0xffffffffu, tm0, 1));
        tm0 = fmaxf(tm0, __shfl_xor_sync(0xffffffffu, tm0, 2));
        tm1 = fmaxf(tm1, __shfl_xor_sync(0xffffffffu, tm1, 1));
        tm1 = fmaxf(tm1, __shfl_xor_sync(0xffffffffu, tm1, 2));

        float nm0 = fmaxf(m0, tm0), nm1 = fmaxf(m1, tm1);
        float al0 = exp2f(m0 - nm0), al1 = exp2f(m1 - nm1);
        m0 = nm0; m1 = nm1;

        float rs0 = 0.f, rs1 = 0.f;
        #pragma unroll
        for (int nt = 0; nt < 8; nt++) {
            sc[nt][0] = exp2f(sc[nt][0] - nm0); rs0 += sc[nt][0];
            sc[nt][1] = exp2f(sc[nt][1] - nm0); rs0 += sc[nt][1];
            sc[nt][2] = exp2f(sc[nt][2] - nm1); rs1 += sc[nt][2];
            sc[nt][3] = exp2f(sc[nt][3] - nm1); rs1 += sc[nt][3];
        }
        rs0 += __shfl_xor_sync(0xffffffffu, rs0, 1);
        rs0 += __shfl_xor_sync(0xffffffffu, rs0, 2);
        rs1 += __shfl_xor_sync(0xffffffffu, rs1, 1);
        rs1 += __shfl_xor_sync(0xffffffffu, rs1, 2);
        l0 = l0 * al0 + rs0;
        l1 = l1 * al1 + rs1;

        #pragma unroll
        for (int nt = 0; nt < 8; nt++) {
            ofr[nt][0] *= al0; ofr[nt][1] *= al0;
            ofr[nt][2] *= al1; ofr[nt][3] *= al1;
        }

        // P C-frag -> half2 A-frag, straight into PV mma
        #pragma unroll
        for (int c = 0; c < 4; c++) {
            __half2 h0 = __floats2half2_rn(sc[2 * c][0], sc[2 * c][1]);
            __half2 h1 = __floats2half2_rn(sc[2 * c][2], sc[2 * c][3]);
            __half2 h2 = __floats2half2_rn(sc[2 * c + 1][0], sc[2 * c + 1][1]);
            __half2 h3 = __floats2half2_rn(sc[2 * c + 1][2], sc[2 * c + 1][3]);
            uint32_t pa0 = *(uint32_t*)&h0, pa1 = *(uint32_t*)&h1;
            uint32_t pa2 = *(uint32_t*)&h2, pa3 = *(uint32_t*)&h3;
            #pragma unroll
            for (int dp = 0; dp < 4; dp++) {
                uint32_t r0, r1, r2, r3;
                ldm_x4(r0, r1, r2, r3,
                       vStage + (uint32_t)(dp * 16 * AQ * 4 + c * 32));
                mma_f16(ofr[2 * dp],     pa0, pa1, pa2, pa3, r0, r2);
                mma_f16(ofr[2 * dp + 1], pa0, pa1, pa2, pa3, r1, r3);
            }
        }

        if (more) {
            uint32_t* KsN = Ks + (s ^ 1) * 64 * AQ;
            uint32_t* VtN = Vt + (s ^ 1) * 64 * AQ;
            #pragma unroll
            for (int r = 0; r < 2; r++) {
                int idx = tid + r * 256, row = idx >> 3, c = idx & 7;
                *(uint4*)&KsN[row * AQ + c * 4] = pk[r];
            }
            __half ha[8], hb[8];
            *(uint4*)ha = pva; *(uint4*)hb = pvb;
            #pragma unroll
            for (int j = 0; j < 8; j++) {
                __half2 p = __halves2half2(ha[j], hb[j]);
                VtN[(dg * 8 + j) * AQ + kp] = *(uint32_t*)&p;
            }
            __syncthreads();
        }
    }

    const float inv0 = 1.f / l0, inv1 = 1.f / l1;
    const int row0 = q0 + wq + g;
    #pragma unroll
    for (int dt = 0; dt < 8; dt++) {
        int col = h * HD + dt * 8 + 2 * t;
        __half2 v0 = __floats2half2_rn(ofr[dt][0] * inv0, ofr[dt][1] * inv0);
        *(uint32_t*)&out[((size_t)bb * SEQ + row0) * DM + col] = *(uint32_t*)&v0;
        __half2 v1 = __floats2half2_rn(ofr[dt][2] * inv1, ofr[dt][3] * inv1);
        *(uint32_t*)&out[((size_t)bb * SEQ + row0 + 8) * DM + col] = *(uint32_t*)&v1;
    }
}

// ----------------------------------------------------------------------------
extern "C" void kernel_launch(void* const* d_in, const int* in_sizes, int n_in,
                              void* d_out, int out_size) {
    const float* q  = (const float*)d_in[0];
    const float* k  = (const float*)d_in[1];
    const float* v  = (const float*)d_in[2];
    const float* Wq = (const float*)d_in[3];
    const float* bq = (const float*)d_in[4];
    const float* Wk = (const float*)d_in[5];
    const float* bk = (const float*)d_in[6];
    const float* Wv = (const float*)d_in[7];
    const float* bv = (const float*)d_in[8];
    const float* Wo = (const float*)d_in[9];
    const float* bo = (const float*)d_in[10];
    float* out = (float*)d_out;

    __half *aq, *ak, *av, *w0, *w1, *w2, *wo, *qh, *kh, *vh, *ao;
    cudaGetSymbolAddress((void**)&aq, g_aq);
    cudaGetSymbolAddress((void**)&ak, g_ak);
    cudaGetSymbolAddress((void**)&av, g_av);
    cudaGetSymbolAddress((void**)&w0, g_wt0);
    cudaGetSymbolAddress((void**)&w1, g_wt1);
    cudaGetSymbolAddress((void**)&w2, g_wt2);
    cudaGetSymbolAddress((void**)&wo, g_wto);
    cudaGetSymbolAddress((void**)&qh, g_qh);
    cudaGetSymbolAddress((void**)&kh, g_kh);
    cudaGetSymbolAddress((void**)&vh, g_vh);
    cudaGetSymbolAddress((void**)&ao, g_ao);

    const float QSCALE = 0.125f * 1.44269504088896f;  // 1/sqrt(64) * log2(e)
    const int n8 = MTOT * DM / 8;

    cudaFuncSetAttribute(attn_h, cudaFuncAttributeMaxDynamicSharedMemorySize,
                         ATTN_SMEM_BYTES);
    cudaFuncSetAttribute(gemm3, cudaFuncAttributeMaxDynamicSharedMemorySize,
                         GEMM_SMEM);
    cudaFuncSetAttribute(gemm1, cudaFuncAttributeMaxDynamicSharedMemorySize,
                         GEMM_SMEM);

    conv3<<<dim3(n8 / 256, 3), 256>>>(q, k, v, aq, ak, av, n8);
    trans3<<<dim3(DM / 32, DM / 32, 3), dim3(32, 8)>>>(Wq, Wk, Wv, w0, w1, w2, QSCALE);
    gemm3<<<dim3(DM / 128, MTOT / 128, 3), 256, GEMM_SMEM>>>(aq, ak, av, w0, w1, w2,
                                                  bq, bk, bv, qh, kh, vh, QSCALE);
    trans1<<<dim3(DM / 32, DM / 32), dim3(32, 8)>>>(Wo, wo);

    attn_h<<<dim3(SEQ / 128, NH, BATCH), 256, ATTN_SMEM_BYTES>>>(qh, kh, vh, ao);

    gemm1<<<dim3(DM / 128, MTOT / 128), 256, GEMM_SMEM>>>(ao, wo, bo, out);
}

// round 16
// speedup vs baseline: 6.4848x; 1.0575x over previous
#include <cuda_runtime.h>
#include <cuda_fp16.h>
#include <math.h>
#include <stdint.h>

#define BATCH 2
#define SEQ   2048
#define DM    1024
#define NH    16
#define HD    64
#define MTOT  (BATCH*SEQ)   // 4096

// ---------------- scratch (allocation-free) ----------------
__device__ __half g_aq[MTOT * DM];
__device__ __half g_ak[MTOT * DM];
__device__ __half g_av[MTOT * DM];
__device__ __half g_wt0[DM * DM];
__device__ __half g_wt1[DM * DM];
__device__ __half g_wt2[DM * DM];
__device__ __half g_wto[DM * DM];
__device__ __half g_qh[MTOT * DM];
__device__ __half g_kh[MTOT * DM];
__device__ __half g_vh[MTOT * DM];
__device__ __half g_ao[MTOT * DM];

// fp16 mma m16n8k16, fp32 accum
__device__ __forceinline__ void mma_f16(float d[4],
    uint32_t a0, uint32_t a1, uint32_t a2, uint32_t a3,
    uint32_t b0, uint32_t b1) {
    asm volatile(
        "mma.sync.aligned.m16n8k16.row.col.f32.f16.f16.f32 "
        "{%0,%1,%2,%3}, {%4,%5,%6,%7}, {%8,%9}, {%0,%1,%2,%3};\n"
        : "+f"(d[0]), "+f"(d[1]), "+f"(d[2]), "+f"(d[3])
        : "r"(a0), "r"(a1), "r"(a2), "r"(a3), "r"(b0), "r"(b1));
}

__device__ __forceinline__ void ldm_x4(uint32_t& r0, uint32_t& r1,
                                       uint32_t& r2, uint32_t& r3, uint32_t addr) {
    asm volatile("ldmatrix.sync.aligned.m8n8.x4.shared.b16 {%0,%1,%2,%3}, [%4];"
        : "=r"(r0), "=r"(r1), "=r"(r2), "=r"(r3) : "r"(addr));
}
__device__ __forceinline__ void ldm_x4_t(uint32_t& r0, uint32_t& r1,
                                         uint32_t& r2, uint32_t& r3, uint32_t addr) {
    asm volatile("ldmatrix.sync.aligned.m8n8.x4.trans.shared.b16 {%0,%1,%2,%3}, [%4];"
        : "=r"(r0), "=r"(r1), "=r"(r2), "=r"(r3) : "r"(addr));
}
__device__ __forceinline__ uint32_t sm_u32(const void* p) {
    return (uint32_t)__cvta_generic_to_shared(p);
}
__device__ __forceinline__ void cpa16(uint32_t dst, const void* src) {
    asm volatile("cp.async.cg.shared.global [%0], [%1], 16;" :: "r"(dst), "l"(src));
}
#define CP_COMMIT() asm volatile("cp.async.commit_group;" ::: "memory")
#define CP_WAIT1()  asm volatile("cp.async.wait_group 1;" ::: "memory")

// ---------------- prep kernels ----------------
__global__ __launch_bounds__(256)
void conv3(const float* __restrict__ q, const float* __restrict__ k,
           const float* __restrict__ v, __half* __restrict__ oq,
           __half* __restrict__ ok, __half* __restrict__ ov, int n8) {
    int i = blockIdx.x * 256 + threadIdx.x;
    if (i >= n8) return;
    const float* in = (blockIdx.y == 0) ? q : (blockIdx.y == 1) ? k : v;
    __half* out = (blockIdx.y == 0) ? oq : (blockIdx.y == 1) ? ok : ov;
    float4 v0 = ((const float4*)in)[2 * i];
    float4 v1 = ((const float4*)in)[2 * i + 1];
    __half2 p0 = __floats2half2_rn(v0.x, v0.y);
    __half2 p1 = __floats2half2_rn(v0.z, v0.w);
    __half2 p2 = __floats2half2_rn(v1.x, v1.y);
    __half2 p3 = __floats2half2_rn(v1.z, v1.w);
    uint4 o;
    o.x = *(uint32_t*)&p0; o.y = *(uint32_t*)&p1;
    o.z = *(uint32_t*)&p2; o.w = *(uint32_t*)&p3;
    ((uint4*)out)[i] = o;
}

// W[K][N] fp32 -> Wt[N][K] fp16 (scaled)
__device__ __forceinline__ void transpose_body(const float* __restrict__ W,
                                               __half* __restrict__ Wt, float scale) {
    __shared__ float tile[32][33];
    const int k0 = blockIdx.x * 32, n0 = blockIdx.y * 32;
    const int tx = threadIdx.x, ty = threadIdx.y;   // 32 x 8
    #pragma unroll
    for (int r = 0; r < 4; r++)
        tile[ty + 8 * r][tx] = W[(size_t)(k0 + ty + 8 * r) * DM + n0 + tx];
    __syncthreads();
    #pragma unroll
    for (int r = 0; r < 4; r++)
        Wt[(size_t)(n0 + ty + 8 * r) * DM + k0 + tx] =
            __float2half_rn(tile[tx][ty + 8 * r] * scale);
}

__global__ __launch_bounds__(256)
void trans3(const float* __restrict__ W0, const float* __restrict__ W1,
            const float* __restrict__ W2, __half* __restrict__ T0,
            __half* __restrict__ T1, __half* __restrict__ T2, float qs) {
    const int z = blockIdx.z;
    const float* W = (z == 0) ? W0 : (z == 1) ? W1 : W2;
    __half* T = (z == 0) ? T0 : (z == 1) ? T1 : T2;
    transpose_body(W, T, (z == 0) ? qs : 1.f);
}

__global__ __launch_bounds__(256)
void trans1(const float* __restrict__ W, __half* __restrict__ T) {
    transpose_body(W, T, 1.f);
}

// ---------------- fp16 GEMM (cp.async 3-stage, BK=64, 16 chunks) ----------------
// CTA 128x128, 8 warps (4x2), warp 32x64. Row stride 36 u32 = 144 B.
#define PSTR 36
#define NCHUNK 16                           // DM / 64
#define TILE_U32 (128 * PSTR)               // one 128x64 fp16 tile
#define STAGE_BYTES (2 * TILE_U32 * 4)      // A+B = 36864
#define GEMM_SMEM (3 * STAGE_BYTES)         // 110592

__device__ __forceinline__ void gemm_body(const __half* __restrict__ A,
        const __half* __restrict__ Wt, const float* __restrict__ bias, float bscale,
        float* __restrict__ Cf, __half* __restrict__ Ch) {
    extern __shared__ uint32_t gsm[];
    const int tid = threadIdx.x;
    const int wid = tid >> 5, lane = tid & 31, g = lane >> 2, t = lane & 3;
    const int lrow = lane & 15, lhi = lane >> 4;
    const int n0 = blockIdx.x * 128, m0 = blockIdx.y * 128;
    const int wm = (wid >> 1) * 32, wn = (wid & 1) * 64;

    const uint32_t smBase = sm_u32(gsm);

    auto issue = [&](int c, int s) {
        const uint32_t aB = smBase + s * STAGE_BYTES;
        const uint32_t bB = aB + TILE_U32 * 4;
        #pragma unroll
        for (int it = 0; it < 4; it++) {
            int idx = tid + it * 256;            // 0..1023
            int row = idx >> 3, col = idx & 7;
            uint32_t off = (uint32_t)((row * PSTR + col * 4) * 4);
            cpa16(aB + off, &A[(size_t)(m0 + row) * DM + c * 64 + col * 8]);
            cpa16(bB + off, &Wt[(size_t)(n0 + row) * DM + c * 64 + col * 8]);
        }
        CP_COMMIT();
    };

    issue(0, 0);
    issue(1, 1);

    float acc[16][4] = {};
    const uint32_t aOff = (uint32_t)(((wm + lrow) * PSTR + lhi * 4) * 4);
    const uint32_t bOff = (uint32_t)(TILE_U32 * 4 + ((wn + lrow) * PSTR + lhi * 4) * 4);

    #pragma unroll 1
    for (int c = 0; c < NCHUNK; c++) {
        const int st = c - (c / 3) * 3;
        CP_WAIT1();
        __syncthreads();
        if (c + 2 < NCHUNK) {
            int cn = c + 2;
            issue(cn, cn - (cn / 3) * 3);
        } else {
            CP_COMMIT();   // empty group: keeps wait_group 1 sound at the tail
        }
        const uint32_t aB = smBase + st * STAGE_BYTES + aOff;
        const uint32_t bB = smBase + st * STAGE_BYTES + bOff;
        #pragma unroll
        for (int kk = 0; kk < 4; kk++) {
            uint32_t af[2][4], bf[8][2];
            #pragma unroll
            for (int mt = 0; mt < 2; mt++)
                ldm_x4(af[mt][0], af[mt][1], af[mt][2], af[mt][3],
                       aB + (uint32_t)(mt * 16 * PSTR * 4 + kk * 32));
            #pragma unroll
            for (int np = 0; np < 4; np++) {
                uint32_t r0, r1, r2, r3;
                ldm_x4(r0, r1, r2, r3, bB + (uint32_t)(np * 16 * PSTR * 4 + kk * 32));
                bf[2 * np][0] = r0; bf[2 * np + 1][0] = r1;
                bf[2 * np][1] = r2; bf[2 * np + 1][1] = r3;
            }
            #pragma unroll
            for (int mt = 0; mt < 2; mt++)
                #pragma unroll
                for (int nt = 0; nt < 8; nt++)
                    mma_f16(acc[mt * 8 + nt], af[mt][0], af[mt][1], af[mt][2], af[mt][3],
                            bf[nt][0], bf[nt][1]);
        }
    }

    #pragma unroll
    for (int mt = 0; mt < 2; mt++) {
        int row = m0 + wm + mt * 16 + g;
        #pragma unroll
        for (int nt = 0; nt < 8; nt++) {
            int col = n0 + wn + nt * 8 + 2 * t;
            float b0 = bias[col] * bscale, b1 = bias[col + 1] * bscale;
            float* a = acc[mt * 8 + nt];
            float v00 = a[0] + b0, v01 = a[1] + b1;
            float v10 = a[2] + b0, v11 = a[3] + b1;
            if (Cf) {
                float2 x0 = { v00, v01 };
                *(float2*)&Cf[(size_t)row * DM + col] = x0;
                float2 x1 = { v10, v11 };
                *(float2*)&Cf[(size_t)(row + 8) * DM + col] = x1;
            }
            if (Ch) {
                __half2 h0 = __floats2half2_rn(v00, v01);
                *(uint32_t*)&Ch[(size_t)row * DM + col] = *(uint32_t*)&h0;
                __half2 h1 = __floats2half2_rn(v10, v11);
                *(uint32_t*)&Ch[(size_t)(row + 8) * DM + col] = *(uint32_t*)&h1;
            }
        }
    }
}

__global__ __launch_bounds__(256, 2)
void gemm3(const __half* __restrict__ aq, const __half* __restrict__ ak,
           const __half* __restrict__ av, const __half* __restrict__ w0,
           const __half* __restrict__ w1, const __half* __restrict__ w2,
           const float* __restrict__ bq, const float* __restrict__ bk,
           const float* __restrict__ bv, __half* __restrict__ oq,
           __half* __restrict__ ok, __half* __restrict__ ov, float qscale) {
    const int z = blockIdx.z;
    const __half* A  = (z == 0) ? aq : (z == 1) ? ak : av;
    const __half* Wt = (z == 0) ? w0 : (z == 1) ? w1 : w2;
    const float* bias = (z == 0) ? bq : (z == 1) ? bk : bv;
    __half* Ch = (z == 0) ? oq : (z == 1) ? ok : ov;
    gemm_body(A, Wt, bias, (z == 0) ? qscale : 1.f, nullptr, Ch);
}

__global__ __launch_bounds__(256, 2)
void gemm1(const __half* __restrict__ A, const __half* __restrict__ Wt,
           const float* __restrict__ bias, float* __restrict__ Cf) {
    gemm_body(A, Wt, bias, 1.f, Cf, nullptr);
}

// ---------------- fp16 flash attention ----------------
// causal, cp.async 3-stage K/V, ldmatrix(+trans for V), h2exp2 softmax.
// CTA = 128 queries of one (b,h); 8 warps, warp = 16 queries x 64 keys.
// Smem: Q[128][36] + 3 stages x (K[64][36] + V[64][36] raw [key][d]).
#define AQ 36
#define ASTG (2 * 64 * AQ)                       // u32 per stage (K+V) = 4608
#define ASTB (ASTG * 4)                          // 18432 B
#define ATTN_SMEM_BYTES ((128 * AQ + 3 * ASTG) * 4)   // 73728

__global__ __launch_bounds__(256, 2)
void attn_h(const __half* __restrict__ qh, const __half* __restrict__ kh,
            const __half* __restrict__ vh, __half* __restrict__ out) {
    extern __shared__ uint32_t smA[];
    uint32_t* Qs = smA;                          // [128][AQ]

    const int tid = threadIdx.x;
    const int w = tid >> 5, lane = tid & 31, g = lane >> 2, t = lane & 3;
    const int lrow = lane & 15, lhi = lane >> 4;
    const int qb = blockIdx.x, h = blockIdx.y, bb = blockIdx.z;
    const int q0 = qb * 128, wq = w * 16;

    const __half* Qb = qh + (size_t)bb * SEQ * DM + h * HD;
    const __half* Kb = kh + (size_t)bb * SEQ * DM + h * HD;
    const __half* Vb = vh + (size_t)bb * SEQ * DM + h * HD;

    const uint32_t smBase = sm_u32(smA);
    const uint32_t stage0 = smBase + 128 * AQ * 4;

    const int ntiles = 2 * qb + 2;

    // issue K/V tile jt into stage s (cp.async, raw [key][d] layout)
    auto issue = [&](int jt, int s) {
        const uint32_t kB = stage0 + s * ASTB;
        const uint32_t vB = kB + 64 * AQ * 4;
        const int j0 = jt * 64;
        #pragma unroll
        for (int it = 0; it < 2; it++) {
            int idx = tid + it * 256;            // 0..511
            int row = idx >> 3, col = idx & 7;
            uint32_t off = (uint32_t)((row * AQ + col * 4) * 4);
            cpa16(kB + off, &Kb[(size_t)(j0 + row) * DM + col * 8]);
            cpa16(vB + off, &Vb[(size_t)(j0 + row) * DM + col * 8]);
        }
        CP_COMMIT();
    };

    // Q tile -> smem (plain stores; ordered by first loop barrier)
    #pragma unroll
    for (int r = 0; r < 4; r++) {
        int idx = tid + r * 256, row = idx >> 3, c = idx & 7;
        uint4 v = *(const uint4*)&Qb[(size_t)(q0 + row) * DM + c * 8];
        *(uint4*)&Qs[row * AQ + c * 4] = v;
    }

    issue(0, 0);
    issue(1, 1);

    const uint32_t qBase = smBase + (uint32_t)(((wq + lrow) * AQ + lhi * 4) * 4);
    const uint32_t kFrag = stage0 + (uint32_t)((lrow * AQ + lhi * 4) * 4);
    const uint32_t vFrag = stage0 + (uint32_t)(64 * AQ * 4 + lrow * AQ * 4 + lhi * 16);

    float ofr[8][4] = {};
    float m0 = -1e30f, m1 = -1e30f, l0 = 0.f, l1 = 0.f;

    #pragma unroll 1
    for (int jt = 0; jt < ntiles; jt++) {
        const int j0 = jt * 64;
        const int st = jt - (jt / 3) * 3;
        CP_WAIT1();
        __syncthreads();
        if (jt + 2 < ntiles) {
            int jn = jt + 2;
            issue(jn, jn - (jn / 3) * 3);
        } else {
            CP_COMMIT();   // empty group keeps wait_group 1 sound at the tail
        }

        const uint32_t kStage = kFrag + st * ASTB;
        const uint32_t vStage = vFrag + st * ASTB;

        // S = Q K^T
        float sc[8][4] = {};
        #pragma unroll
        for (int kk = 0; kk < 4; kk++) {
            uint32_t a0, a1, a2, a3;
            ldm_x4(a0, a1, a2, a3, qBase + (uint32_t)(kk * 32));
            #pragma unroll
            for (int np = 0; np < 4; np++) {
                uint32_t r0, r1, r2, r3;
                ldm_x4(r0, r1, r2, r3,
                       kStage + (uint32_t)(np * 16 * AQ * 4 + kk * 32));
                mma_f16(sc[2 * np],     a0, a1, a2, a3, r0, r2);
                mma_f16(sc[2 * np + 1], a0, a1, a2, a3, r1, r3);
            }
        }

        // causal mask
        if (j0 + 63 > q0 + wq) {
            int r0 = q0 + wq + g, r1 = r0 + 8;
            #pragma unroll
            for (int nt = 0; nt < 8; nt++) {
                int key = j0 + nt * 8 + 2 * t;
                if (key > r0)     sc[nt][0] = -1e30f;
                if (key + 1 > r0) sc[nt][1] = -1e30f;
                if (key > r1)     sc[nt][2] = -1e30f;
                if (key + 1 > r1) sc[nt][3] = -1e30f;
            }
        }

        // online softmax (base-2; scale folded into Wq/bq)
        float tm0 = -1e30f, tm1 = -1e30f;
        #pragma unroll
        for (int nt = 0; nt < 8; nt++) {
            tm0 = fmaxf(tm0, fmaxf(sc[nt][0], sc[nt][1]));
            tm1 = fmaxf(tm1, fmaxf(sc[nt][2], sc[nt][3]));
        }
        tm0 = fmaxf(tm0, __shfl_xor_sync(0xffffffffu, tm0, 1));
        tm0 = fmaxf(tm0, __shfl_xor_sync(0xffffffffu, tm0, 2));
        tm1 = fmaxf(tm1, __shfl_xor_sync(0xffffffffu, tm1, 1));
        tm1 = fmaxf(tm1, __shfl_xor_sync(0xffffffffu, tm1, 2));

        float nm0 = fmaxf(m0, tm0), nm1 = fmaxf(m1, tm1);
        float al0 = exp2f(m0 - nm0), al1 = exp2f(m1 - nm1);
        m0 = nm0; m1 = nm1;

        // P = 2^(S - m) computed directly in packed fp16 (ex2.approx.f16x2);
        // the resulting half2 IS the PV A-fragment. Row sums in fp32.
        uint32_t pl[8], ph_[8];
        float rs0 = 0.f, rs1 = 0.f;
        #pragma unroll
        for (int nt = 0; nt < 8; nt++) {
            __half2 x0 = __floats2half2_rn(sc[nt][0] - nm0, sc[nt][1] - nm0);
            __half2 p0 = h2exp2(x0);
            pl[nt] = *(uint32_t*)&p0;
            float2 f0 = __half22float2(p0);
            rs0 += f0.x + f0.y;
            __half2 x1 = __floats2half2_rn(sc[nt][2] - nm1, sc[nt][3] - nm1);
            __half2 p1 = h2exp2(x1);
            ph_[nt] = *(uint32_t*)&p1;
            float2 f1 = __half22float2(p1);
            rs1 += f1.x + f1.y;
        }
        rs0 += __shfl_xor_sync(0xffffffffu, rs0, 1);
        rs0 += __shfl_xor_sync(0xffffffffu, rs0, 2);
        rs1 += __shfl_xor_sync(0xffffffffu, rs1, 1);
        rs1 += __shfl_xor_sync(0xffffffffu, rs1, 2);
        l0 = l0 * al0 + rs0;
        l1 = l1 * al1 + rs1;

        #pragma unroll
        for (int nt = 0; nt < 8; nt++) {
            ofr[nt][0] *= al0; ofr[nt][1] *= al0;
            ofr[nt][2] *= al1; ofr[nt][3] *= al1;
        }

        // O += P @ V  (V raw [key][d]; ldmatrix.trans gives V^T B-frags)
        #pragma unroll
        for (int c = 0; c < 4; c++) {
            uint32_t pa0 = pl[2 * c], pa1 = ph_[2 * c];
            uint32_t pa2 = pl[2 * c + 1], pa3 = ph_[2 * c + 1];
            #pragma unroll
            for (int dp = 0; dp < 4; dp++) {
                uint32_t r0, r1, r2, r3;
                ldm_x4_t(r0, r1, r2, r3,
                         vStage + (uint32_t)(c * 16 * AQ * 4 + dp * 32));
                mma_f16(ofr[2 * dp],     pa0, pa1, pa2, pa3, r0, r1);
                mma_f16(ofr[2 * dp + 1], pa0, pa1, pa2, pa3, r2, r3);
            }
        }
    }

    const float inv0 = 1.f / l0, inv1 = 1.f / l1;
    const int row0 = q0 + wq + g;
    #pragma unroll
    for (int dt = 0; dt < 8; dt++) {
        int col = h * HD + dt * 8 + 2 * t;
        __half2 v0 = __floats2half2_rn(ofr[dt][0] * inv0, ofr[dt][1] * inv0);
        *(uint32_t*)&out[((size_t)bb * SEQ + row0) * DM + col] = *(uint32_t*)&v0;
        __half2 v1 = __floats2half2_rn(ofr[dt][2] * inv1, ofr[dt][3] * inv1);
        *(uint32_t*)&out[((size_t)bb * SEQ + row0 + 8) * DM + col] = *(uint32_t*)&v1;
    }
}

// ----------------------------------------------------------------------------
extern "C" void kernel_launch(void* const* d_in, const int* in_sizes, int n_in,
                              void* d_out, int out_size) {
    const float* q  = (const float*)d_in[0];
    const float* k  = (const float*)d_in[1];
    const float* v  = (const float*)d_in[2];
    const float* Wq = (const float*)d_in[3];
    const float* bq = (const float*)d_in[4];
    const float* Wk = (const float*)d_in[5];
    const float* bk = (const float*)d_in[6];
    const float* Wv = (const float*)d_in[7];
    const float* bv = (const float*)d_in[8];
    const float* Wo = (const float*)d_in[9];
    const float* bo = (const float*)d_in[10];
    float* out = (float*)d_out;

    __half *aq, *ak, *av, *w0, *w1, *w2, *wo, *qh, *kh, *vh, *ao;
    cudaGetSymbolAddress((void**)&aq, g_aq);
    cudaGetSymbolAddress((void**)&ak, g_ak);
    cudaGetSymbolAddress((void**)&av, g_av);
    cudaGetSymbolAddress((void**)&w0, g_wt0);
    cudaGetSymbolAddress((void**)&w1, g_wt1);
    cudaGetSymbolAddress((void**)&w2, g_wt2);
    cudaGetSymbolAddress((void**)&wo, g_wto);
    cudaGetSymbolAddress((void**)&qh, g_qh);
    cudaGetSymbolAddress((void**)&kh, g_kh);
    cudaGetSymbolAddress((void**)&vh, g_vh);
    cudaGetSymbolAddress((void**)&ao, g_ao);

    const float QSCALE = 0.125f * 1.44269504088896f;  // 1/sqrt(64) * log2(e)
    const int n8 = MTOT * DM / 8;

    cudaFuncSetAttribute(attn_h, cudaFuncAttributeMaxDynamicSharedMemorySize,
                         ATTN_SMEM_BYTES);
    cudaFuncSetAttribute(gemm3, cudaFuncAttributeMaxDynamicSharedMemorySize,
                         GEMM_SMEM);
    cudaFuncSetAttribute(gemm1, cudaFuncAttributeMaxDynamicSharedMemorySize,
                         GEMM_SMEM);

    // trans1 moved before gemm3 so the profiler's fixed capture slot (4th
    // launch) lands on gemm3 next round.
    conv3<<<dim3(n8 / 256, 3), 256>>>(q, k, v, aq, ak, av, n8);
    trans3<<<dim3(DM / 32, DM / 32, 3), dim3(32, 8)>>>(Wq, Wk, Wv, w0, w1, w2, QSCALE);
    trans1<<<dim3(DM / 32, DM / 32), dim3(32, 8)>>>(Wo, wo);
    gemm3<<<dim3(DM / 128, MTOT / 128, 3), 256, GEMM_SMEM>>>(aq, ak, av, w0, w1, w2,
                                                  bq, bk, bv, qh, kh, vh, QSCALE);
    attn_h<<<dim3(SEQ / 128, NH, BATCH), 256, ATTN_SMEM_BYTES>>>(qh, kh, vh, ao);

    gemm1<<<dim3(DM / 128, MTOT / 128), 256, GEMM_SMEM>>>(ao, wo, bo, out);
}